// round 11
// baseline (speedup 1.0000x reference)
#include <cuda_runtime.h>
#include <cuda_bf16.h>
#include <cstdint>

#define NB 4
#define GDIM 7
#define NREG 49
#define HH 224
#define CC 256
#define NQ 100
#define HSTRIDE (HH*CC)
#define THREADS 128
#define NPASS 32            // 32 keys per pass (one image row-strip)
#define PAD 264             // bf16 row stride (528B -> conflict-free ldmatrix)

#define OUT_ELEMS (NB*NREG*NQ*CC)
#define POS_ELEMS (NREG*2)

// smem byte offsets
#define SQ_HI 0
#define SQ_LO 33792         // 64*264*2
#define SK_HI 67584
#define SK_LO 84480         // SK_HI + 32*264*2
#define SMEM_BYTES 101376   // 2 CTAs/SM: 202752 <= 227328
#define QHILO 33792
#define KHILO 16896

// ---------------- helpers ----------------
__device__ __forceinline__ uint32_t smem_u32(const void* p) {
    uint32_t a;
    asm("{ .reg .u64 t; cvta.to.shared.u64 t, %1; cvt.u32.u64 %0, t; }" : "=r"(a) : "l"(p));
    return a;
}
__device__ __forceinline__ uint32_t cvt2(float a, float b) {  // {lo=a, hi=b}
    uint32_t r; asm("cvt.rn.bf16x2.f32 %0, %2, %1;" : "=r"(r) : "f"(a), "f"(b));
    return r;
}
__device__ __forceinline__ void split2(float a, float b, uint32_t& hi, uint32_t& lo) {
    hi = cvt2(a, b);
    float ah = __uint_as_float(hi << 16);
    float bh = __uint_as_float(hi & 0xFFFF0000u);
    lo = cvt2(a - ah, b - bh);
}
__device__ __forceinline__ void ldsm4(uint32_t r[4], uint32_t a) {
    asm volatile("ldmatrix.sync.aligned.m8n8.x4.shared.b16 {%0,%1,%2,%3}, [%4];"
        : "=r"(r[0]), "=r"(r[1]), "=r"(r[2]), "=r"(r[3]) : "r"(a));
}
__device__ __forceinline__ void ldsm4t(uint32_t r[4], uint32_t a) {
    asm volatile("ldmatrix.sync.aligned.m8n8.x4.trans.shared.b16 {%0,%1,%2,%3}, [%4];"
        : "=r"(r[0]), "=r"(r[1]), "=r"(r[2]), "=r"(r[3]) : "r"(a));
}
__device__ __forceinline__ void mma16816(float* c, const uint32_t* a, uint32_t b0, uint32_t b1) {
    asm volatile("mma.sync.aligned.m16n8k16.row.col.f32.bf16.bf16.f32 "
        "{%0,%1,%2,%3}, {%4,%5,%6,%7}, {%8,%9}, {%0,%1,%2,%3};"
        : "+f"(c[0]), "+f"(c[1]), "+f"(c[2]), "+f"(c[3])
        : "r"(a[0]), "r"(a[1]), "r"(a[2]), "r"(a[3]), "r"(b0), "r"(b1));
}

// ================= kernel =================
// grid = 392 (196 regions x 2 q-tiles of 64 rows), 128 threads (4 warps x 16 rows)
// 2 CTAs resident per SM
__global__ void __launch_bounds__(THREADS, 2)
attn_kernel(const float* __restrict__ images,
            const float* __restrict__ queries,
            float* __restrict__ out)
{
    extern __shared__ char smem[];
    const uint32_t sa = smem_u32(smem);

    const int bx     = blockIdx.x;
    const int region = bx >> 1;
    const int qtile  = bx & 1;
    const int b  = region / NREG;
    const int n  = region % NREG;
    const int gi = n / GDIM;
    const int gj = n % GDIM;

    const int tid  = threadIdx.x;
    const int lane = tid & 31;
    const int warp = tid >> 5;          // 0..3, rows warp*16..warp*16+15

    // ---- stage Q hi/lo: [64 rows][PAD] bf16 each ----
    for (int id = tid; id < 64 * 128; id += THREADS) {   // channel pairs
        int q = id >> 7;
        int c = (id & 127) * 2;
        int qg = qtile * 64 + q;
        float x = 0.0f, y = 0.0f;
        if (qg < NQ) {
            float2 v = *(const float2*)&queries[qg * CC + c];
            x = v.x; y = v.y;
        }
        uint32_t h, l;
        split2(x, y, h, l);
        uint32_t o = (q * PAD + c) * 2;
        *(uint32_t*)(smem + SQ_HI + o) = h;
        *(uint32_t*)(smem + SQ_LO + o) = l;
    }

    // ---- per-lane ldmatrix base addresses ----
    const uint32_t qA = sa + SQ_HI +
        (((warp * 16) + (lane & 15)) * PAD + (lane >> 4) * 8) * 2;
    const uint32_t kB = sa + SK_HI +
        (((lane & 7) + (lane >> 4) * 8) * PAD + ((lane >> 3) & 1) * 8) * 2;
    const uint32_t vB = sa + SK_HI +
        (((lane & 7) + ((lane >> 3) & 1) * 8) * PAD + (lane >> 4) * 8) * 2;

    const float* imgbase = images + ((size_t)(b * HH + gi * 32) * HH + gj * 32) * CC;

    // ---- state ----
    float acc[32][4];                   // O [16 rows x 256 ch] fragment
    #pragma unroll
    for (int j = 0; j < 32; j++)
        #pragma unroll
        for (int k = 0; k < 4; k++) acc[j][k] = 0.0f;
    float m1 = -1e30f, m2 = -1e30f, l1 = 0.0f, l2 = 0.0f;

    // prologue: prefetch pass 0 (32 keys = one contiguous row strip)
    float4 v[16];
    {
        const float4* g0 = (const float4*)imgbase;
        #pragma unroll
        for (int it = 0; it < 16; it++) v[it] = g0[tid + it * THREADS];
    }

    for (int p = 0; p < NPASS; p++) {
        __syncthreads();                // all warps done reading previous K tile
        // ---- deposit prefetched keys as bf16 hi/lo ----
        #pragma unroll
        for (int it = 0; it < 16; it++) {
            int id = tid + it * THREADS;       // 0..2047
            int s = id >> 6, c4 = id & 63;
            uint32_t h0, l0, h1, l1_;
            split2(v[it].x, v[it].y, h0, l0);
            split2(v[it].z, v[it].w, h1, l1_);
            uint32_t o = (s * PAD + c4 * 4) * 2;
            *(uint2*)(smem + SK_HI + o) = make_uint2(h0, h1);
            *(uint2*)(smem + SK_LO + o) = make_uint2(l0, l1_);
        }
        __syncthreads();

        // ---- QK: S[16 x 32], 3-term emulation, 12 independent chains ----
        float shh[4][4], shl[4][4], slh[4][4];
        #pragma unroll
        for (int j = 0; j < 4; j++)
            #pragma unroll
            for (int k = 0; k < 4; k++) { shh[j][k] = 0.f; shl[j][k] = 0.f; slh[j][k] = 0.f; }

        #pragma unroll
        for (int ks = 0; ks < 16; ks++) {
            uint32_t ah[4], al[4];
            ldsm4(ah, qA + ks * 32);
            ldsm4(al, qA + QHILO + ks * 32);
            #pragma unroll
            for (int j = 0; j < 2; j++) {          // 16 keys per iter
                uint32_t bh[4], bl[4];
                uint32_t ko = kB + j * (16 * PAD * 2) + ks * 32;
                ldsm4(bh, ko);
                ldsm4(bl, ko + KHILO);
                mma16816(shh[2*j],   ah, bh[0], bh[1]);
                mma16816(shl[2*j],   ah, bl[0], bl[1]);
                mma16816(slh[2*j],   al, bh[0], bh[1]);
                mma16816(shh[2*j+1], ah, bh[2], bh[3]);
                mma16816(shl[2*j+1], ah, bl[2], bl[3]);
                mma16816(slh[2*j+1], al, bh[2], bh[3]);
            }
        }
        float s_[4][4];
        #pragma unroll
        for (int j = 0; j < 4; j++)
            #pragma unroll
            for (int k = 0; k < 4; k++) s_[j][k] = shh[j][k] + shl[j][k] + slh[j][k];

        // ---- online softmax (rows r=lane>>2 and r+8) ----
        float mx1 = -1e30f, mx2 = -1e30f;
        #pragma unroll
        for (int j = 0; j < 4; j++) {
            mx1 = fmaxf(mx1, fmaxf(s_[j][0], s_[j][1]));
            mx2 = fmaxf(mx2, fmaxf(s_[j][2], s_[j][3]));
        }
        mx1 = fmaxf(mx1, __shfl_xor_sync(0xffffffffu, mx1, 1));
        mx1 = fmaxf(mx1, __shfl_xor_sync(0xffffffffu, mx1, 2));
        mx2 = fmaxf(mx2, __shfl_xor_sync(0xffffffffu, mx2, 1));
        mx2 = fmaxf(mx2, __shfl_xor_sync(0xffffffffu, mx2, 2));
        float m1n = fmaxf(m1, mx1), m2n = fmaxf(m2, mx2);
        float a1 = __expf(m1 - m1n), a2 = __expf(m2 - m2n);
        m1 = m1n; m2 = m2n;

        float sum1 = 0.0f, sum2 = 0.0f;
        #pragma unroll
        for (int j = 0; j < 4; j++) {
            s_[j][0] = __expf(s_[j][0] - m1); sum1 += s_[j][0];
            s_[j][1] = __expf(s_[j][1] - m1); sum1 += s_[j][1];
            s_[j][2] = __expf(s_[j][2] - m2); sum2 += s_[j][2];
            s_[j][3] = __expf(s_[j][3] - m2); sum2 += s_[j][3];
        }
        l1 = l1 * a1 + sum1;
        l2 = l2 * a2 + sum2;

        #pragma unroll
        for (int j = 0; j < 32; j++) {
            acc[j][0] *= a1; acc[j][1] *= a1;
            acc[j][2] *= a2; acc[j][3] *= a2;
        }

        // ---- pack P into PV A-fragments ----
        uint32_t pAh[2][4], pAl[2][4];
        #pragma unroll
        for (int kk = 0; kk < 2; kk++) {
            split2(s_[2*kk][0],   s_[2*kk][1],   pAh[kk][0], pAl[kk][0]);
            split2(s_[2*kk][2],   s_[2*kk][3],   pAh[kk][1], pAl[kk][1]);
            split2(s_[2*kk+1][0], s_[2*kk+1][1], pAh[kk][2], pAl[kk][2]);
            split2(s_[2*kk+1][2], s_[2*kk+1][3], pAh[kk][3], pAl[kk][3]);
        }

        // ---- prefetch next pass NOW: latency hides under PV ----
        if (p + 1 < NPASS) {
            const float4* g0 = (const float4*)(imgbase + (size_t)(p + 1) * HSTRIDE);
            #pragma unroll
            for (int it = 0; it < 16; it++) v[it] = g0[tid + it * THREADS];
        }

        // ---- PV: O += P[16x32] * V[32x256], 3-term ----
        #pragma unroll
        for (int nn = 0; nn < 16; nn++) {
            #pragma unroll
            for (int kk = 0; kk < 2; kk++) {
                uint32_t bh[4], bl[4];
                uint32_t vo = vB + (kk * 16 * PAD + nn * 16) * 2;
                ldsm4t(bh, vo);
                ldsm4t(bl, vo + KHILO);
                mma16816(acc[2*nn],   pAh[kk], bh[0], bh[1]);
                mma16816(acc[2*nn],   pAh[kk], bl[0], bl[1]);
                mma16816(acc[2*nn],   pAl[kk], bh[0], bh[1]);
                mma16816(acc[2*nn+1], pAh[kk], bh[2], bh[3]);
                mma16816(acc[2*nn+1], pAh[kk], bl[2], bl[3]);
                mma16816(acc[2*nn+1], pAl[kk], bh[2], bh[3]);
            }
        }
    }

    // ---- epilogue ----
    l1 += __shfl_xor_sync(0xffffffffu, l1, 1);
    l1 += __shfl_xor_sync(0xffffffffu, l1, 2);
    l2 += __shfl_xor_sync(0xffffffffu, l2, 1);
    l2 += __shfl_xor_sync(0xffffffffu, l2, 2);
    float inv1 = 1.0f / l1, inv2 = 1.0f / l2;

    int r1 = qtile * 64 + warp * 16 + (lane >> 2);
    int r2 = r1 + 8;
    int cb = 2 * (lane & 3);
    if (r1 < NQ) {
        float* o1 = out + ((size_t)region * NQ + r1) * CC + cb;
        #pragma unroll
        for (int j = 0; j < 32; j++)
            *(float2*)(o1 + j * 8) = make_float2(acc[j][0] * inv1, acc[j][1] * inv1);
    }
    if (r2 < NQ) {
        float* o2 = out + ((size_t)region * NQ + r2) * CC + cb;
        #pragma unroll
        for (int j = 0; j < 32; j++)
            *(float2*)(o2 + j * 8) = make_float2(acc[j][2] * inv2, acc[j][3] * inv2);
    }
}

// ---------------- positions (second tuple output) ----------------
__global__ void pos_kernel(float* __restrict__ out, int out_size) {
    int t = threadIdx.x;
    if (t < NREG && out_size >= OUT_ELEMS + POS_ELEMS) {
        out[OUT_ELEMS + 2 * t + 0] = (float)(t / GDIM) * (1.0f / 7.0f);
        out[OUT_ELEMS + 2 * t + 1] = (float)(t % GDIM) * (1.0f / 7.0f);
    }
}

extern "C" void kernel_launch(void* const* d_in, const int* in_sizes, int n_in,
                              void* d_out, int out_size) {
    const float* images  = (const float*)d_in[0];
    const float* queries = (const float*)d_in[1];
    if (n_in >= 2 && in_sizes[0] == NQ * CC) {
        const float* t = images; images = queries; queries = t;
    }
    float* out = (float*)d_out;

    cudaFuncSetAttribute(attn_kernel,
                         cudaFuncAttributeMaxDynamicSharedMemorySize, SMEM_BYTES);

    // pos_kernel first so ncu "-s 5 -c 1" lands on attn_kernel
    pos_kernel<<<1, 64>>>(out, out_size);
    attn_kernel<<<196 * 2, THREADS, SMEM_BYTES>>>(images, queries, out);
}

// round 12
// speedup vs baseline: 1.1424x; 1.1424x over previous
#include <cuda_runtime.h>
#include <cuda_bf16.h>
#include <cstdint>

#define NB 4
#define GDIM 7
#define NREG 49
#define HH 224
#define CC 256
#define NQ 100
#define HSTRIDE (HH*CC)
#define THREADS 128
#define NPASS 32            // 32 keys per pass (one image row-strip)
#define PAD 264             // bf16 row stride (528B -> conflict-free ldmatrix)

#define OUT_ELEMS (NB*NREG*NQ*CC)
#define POS_ELEMS (NREG*2)

// smem byte offsets
#define SQ_HI 0
#define SQ_LO 33792         // 64*264*2
#define SK_HI 67584
#define SK_LO 84480         // SK_HI + 32*264*2
#define SMEM_BYTES 101376   // 2 CTAs/SM
#define QHILO 33792
#define KHILO 16896

// ---------------- helpers ----------------
__device__ __forceinline__ uint32_t smem_u32(const void* p) {
    uint32_t a;
    asm("{ .reg .u64 t; cvta.to.shared.u64 t, %1; cvt.u32.u64 %0, t; }" : "=r"(a) : "l"(p));
    return a;
}
__device__ __forceinline__ uint32_t cvt2(float a, float b) {  // {lo=a, hi=b}
    uint32_t r; asm("cvt.rn.bf16x2.f32 %0, %2, %1;" : "=r"(r) : "f"(a), "f"(b));
    return r;
}
__device__ __forceinline__ void split2(float a, float b, uint32_t& hi, uint32_t& lo) {
    hi = cvt2(a, b);
    float ah = __uint_as_float(hi << 16);
    float bh = __uint_as_float(hi & 0xFFFF0000u);
    lo = cvt2(a - ah, b - bh);
}
__device__ __forceinline__ void ldsm4(uint32_t r[4], uint32_t a) {
    asm volatile("ldmatrix.sync.aligned.m8n8.x4.shared.b16 {%0,%1,%2,%3}, [%4];"
        : "=r"(r[0]), "=r"(r[1]), "=r"(r[2]), "=r"(r[3]) : "r"(a));
}
__device__ __forceinline__ void ldsm4t(uint32_t r[4], uint32_t a) {
    asm volatile("ldmatrix.sync.aligned.m8n8.x4.trans.shared.b16 {%0,%1,%2,%3}, [%4];"
        : "=r"(r[0]), "=r"(r[1]), "=r"(r[2]), "=r"(r[3]) : "r"(a));
}
__device__ __forceinline__ void mma16816(float* c, const uint32_t* a, uint32_t b0, uint32_t b1) {
    asm volatile("mma.sync.aligned.m16n8k16.row.col.f32.bf16.bf16.f32 "
        "{%0,%1,%2,%3}, {%4,%5,%6,%7}, {%8,%9}, {%0,%1,%2,%3};"
        : "+f"(c[0]), "+f"(c[1]), "+f"(c[2]), "+f"(c[3])
        : "r"(a[0]), "r"(a[1]), "r"(a[2]), "r"(a[3]), "r"(b0), "r"(b1));
}

// ================= kernel =================
// grid = 392 (196 regions x 2 q-tiles of 64 rows), 128 threads (4 warps x 16 rows)
// 2 CTAs resident per SM
__global__ void __launch_bounds__(THREADS, 2)
attn_kernel(const float* __restrict__ images,
            const float* __restrict__ queries,
            float* __restrict__ out)
{
    extern __shared__ char smem[];
    const uint32_t sa = smem_u32(smem);

    const int bx     = blockIdx.x;
    const int region = bx >> 1;
    const int qtile  = bx & 1;
    const int b  = region / NREG;
    const int n  = region % NREG;
    const int gi = n / GDIM;
    const int gj = n % GDIM;

    const int tid  = threadIdx.x;
    const int lane = tid & 31;
    const int warp = tid >> 5;          // 0..3, rows warp*16..warp*16+15

    // ---- stage Q hi/lo: [64 rows][PAD] bf16 each ----
    for (int id = tid; id < 64 * 128; id += THREADS) {   // channel pairs
        int q = id >> 7;
        int c = (id & 127) * 2;
        int qg = qtile * 64 + q;
        float x = 0.0f, y = 0.0f;
        if (qg < NQ) {
            float2 v = *(const float2*)&queries[qg * CC + c];
            x = v.x; y = v.y;
        }
        uint32_t h, l;
        split2(x, y, h, l);
        uint32_t o = (q * PAD + c) * 2;
        *(uint32_t*)(smem + SQ_HI + o) = h;
        *(uint32_t*)(smem + SQ_LO + o) = l;
    }

    // ---- per-lane ldmatrix base addresses ----
    const uint32_t qA = sa + SQ_HI +
        (((warp * 16) + (lane & 15)) * PAD + (lane >> 4) * 8) * 2;
    const uint32_t kB = sa + SK_HI +
        (((lane & 7) + (lane >> 4) * 8) * PAD + ((lane >> 3) & 1) * 8) * 2;
    const uint32_t vB = sa + SK_HI +
        (((lane & 7) + ((lane >> 3) & 1) * 8) * PAD + (lane >> 4) * 8) * 2;

    const float* imgbase = images + ((size_t)(b * HH + gi * 32) * HH + gj * 32) * CC;

    // ---- state ----
    float acc[32][4];                   // O [16 rows x 256 ch] fragment
    #pragma unroll
    for (int j = 0; j < 32; j++)
        #pragma unroll
        for (int k = 0; k < 4; k++) acc[j][k] = 0.0f;
    float m1 = -1e30f, m2 = -1e30f, l1 = 0.0f, l2 = 0.0f;

    for (int p = 0; p < NPASS; p++) {
        // ---- load 32 keys (one contiguous row-strip) ----
        float4 v[16];
        {
            const float4* g0 = (const float4*)(imgbase + (size_t)p * HSTRIDE);
            #pragma unroll
            for (int it = 0; it < 16; it++) v[it] = g0[tid + it * THREADS];
        }
        __syncthreads();                // prev pass compute done
        #pragma unroll
        for (int it = 0; it < 16; it++) {
            int id = tid + it * THREADS;       // 0..2047
            int s = id >> 6, c4 = id & 63;
            uint32_t h0, l0, h1, l1_;
            split2(v[it].x, v[it].y, h0, l0);
            split2(v[it].z, v[it].w, h1, l1_);
            uint32_t o = (s * PAD + c4 * 4) * 2;
            *(uint2*)(smem + SK_HI + o) = make_uint2(h0, h1);
            *(uint2*)(smem + SK_LO + o) = make_uint2(l0, l1_);
        }
        __syncthreads();

        // ---- QK: S[16 x 32], 3-term emulation, term-major issue order ----
        // (same-C MMAs spaced 4 apart -> HMMA latency covered, no extra chains)
        float s_[4][4];
        #pragma unroll
        for (int j = 0; j < 4; j++)
            #pragma unroll
            for (int k = 0; k < 4; k++) s_[j][k] = 0.0f;

        #pragma unroll
        for (int ks = 0; ks < 16; ks++) {
            uint32_t ah[4], al[4], bh0[4], bl0[4], bh1[4], bl1[4];
            ldsm4(ah, qA + ks * 32);
            ldsm4(al, qA + QHILO + ks * 32);
            ldsm4(bh0, kB + ks * 32);
            ldsm4(bl0, kB + KHILO + ks * 32);
            ldsm4(bh1, kB + 16 * PAD * 2 + ks * 32);
            ldsm4(bl1, kB + KHILO + 16 * PAD * 2 + ks * 32);
            // hi*hi
            mma16816(s_[0], ah, bh0[0], bh0[1]);
            mma16816(s_[1], ah, bh0[2], bh0[3]);
            mma16816(s_[2], ah, bh1[0], bh1[1]);
            mma16816(s_[3], ah, bh1[2], bh1[3]);
            // hi*lo
            mma16816(s_[0], ah, bl0[0], bl0[1]);
            mma16816(s_[1], ah, bl0[2], bl0[3]);
            mma16816(s_[2], ah, bl1[0], bl1[1]);
            mma16816(s_[3], ah, bl1[2], bl1[3]);
            // lo*hi
            mma16816(s_[0], al, bh0[0], bh0[1]);
            mma16816(s_[1], al, bh0[2], bh0[3]);
            mma16816(s_[2], al, bh1[0], bh1[1]);
            mma16816(s_[3], al, bh1[2], bh1[3]);
        }

        // ---- online softmax (rows r=lane>>2 and r+8) ----
        float mx1 = -1e30f, mx2 = -1e30f;
        #pragma unroll
        for (int j = 0; j < 4; j++) {
            mx1 = fmaxf(mx1, fmaxf(s_[j][0], s_[j][1]));
            mx2 = fmaxf(mx2, fmaxf(s_[j][2], s_[j][3]));
        }
        mx1 = fmaxf(mx1, __shfl_xor_sync(0xffffffffu, mx1, 1));
        mx1 = fmaxf(mx1, __shfl_xor_sync(0xffffffffu, mx1, 2));
        mx2 = fmaxf(mx2, __shfl_xor_sync(0xffffffffu, mx2, 1));
        mx2 = fmaxf(mx2, __shfl_xor_sync(0xffffffffu, mx2, 2));
        float m1n = fmaxf(m1, mx1), m2n = fmaxf(m2, mx2);
        float a1 = __expf(m1 - m1n), a2 = __expf(m2 - m2n);
        m1 = m1n; m2 = m2n;

        float sum1 = 0.0f, sum2 = 0.0f;
        #pragma unroll
        for (int j = 0; j < 4; j++) {
            s_[j][0] = __expf(s_[j][0] - m1); sum1 += s_[j][0];
            s_[j][1] = __expf(s_[j][1] - m1); sum1 += s_[j][1];
            s_[j][2] = __expf(s_[j][2] - m2); sum2 += s_[j][2];
            s_[j][3] = __expf(s_[j][3] - m2); sum2 += s_[j][3];
        }
        l1 = l1 * a1 + sum1;
        l2 = l2 * a2 + sum2;

        #pragma unroll
        for (int j = 0; j < 32; j++) {
            acc[j][0] *= a1; acc[j][1] *= a1;
            acc[j][2] *= a2; acc[j][3] *= a2;
        }

        // ---- pack P into PV A-fragments (C->A layout identity) ----
        uint32_t pAh[2][4], pAl[2][4];
        #pragma unroll
        for (int kk = 0; kk < 2; kk++) {
            split2(s_[2*kk][0],   s_[2*kk][1],   pAh[kk][0], pAl[kk][0]);
            split2(s_[2*kk][2],   s_[2*kk][3],   pAh[kk][1], pAl[kk][1]);
            split2(s_[2*kk+1][0], s_[2*kk+1][1], pAh[kk][2], pAl[kk][2]);
            split2(s_[2*kk+1][2], s_[2*kk+1][3], pAh[kk][3], pAl[kk][3]);
        }

        // ---- PV: O += P[16x32] * V[32x256], nn-pair interleave (dist 4) ----
        #pragma unroll
        for (int nn2 = 0; nn2 < 8; nn2++) {
            int n0 = 2 * nn2, n1 = n0 + 1;
            #pragma unroll
            for (int kk = 0; kk < 2; kk++) {
                uint32_t bhA[4], blA[4], bhB[4], blB[4];
                uint32_t voA = vB + (kk * 16 * PAD + n0 * 16) * 2;
                uint32_t voB = vB + (kk * 16 * PAD + n1 * 16) * 2;
                ldsm4t(bhA, voA);
                ldsm4t(blA, voA + KHILO);
                ldsm4t(bhB, voB);
                ldsm4t(blB, voB + KHILO);
                // hi*hi
                mma16816(acc[2*n0],   pAh[kk], bhA[0], bhA[1]);
                mma16816(acc[2*n0+1], pAh[kk], bhA[2], bhA[3]);
                mma16816(acc[2*n1],   pAh[kk], bhB[0], bhB[1]);
                mma16816(acc[2*n1+1], pAh[kk], bhB[2], bhB[3]);
                // hi*lo
                mma16816(acc[2*n0],   pAh[kk], blA[0], blA[1]);
                mma16816(acc[2*n0+1], pAh[kk], blA[2], blA[3]);
                mma16816(acc[2*n1],   pAh[kk], blB[0], blB[1]);
                mma16816(acc[2*n1+1], pAh[kk], blB[2], blB[3]);
                // lo*hi
                mma16816(acc[2*n0],   pAl[kk], bhA[0], bhA[1]);
                mma16816(acc[2*n0+1], pAl[kk], bhA[2], bhA[3]);
                mma16816(acc[2*n1],   pAl[kk], bhB[0], bhB[1]);
                mma16816(acc[2*n1+1], pAl[kk], bhB[2], bhB[3]);
            }
        }
    }

    // ---- epilogue ----
    l1 += __shfl_xor_sync(0xffffffffu, l1, 1);
    l1 += __shfl_xor_sync(0xffffffffu, l1, 2);
    l2 += __shfl_xor_sync(0xffffffffu, l2, 1);
    l2 += __shfl_xor_sync(0xffffffffu, l2, 2);
    float inv1 = 1.0f / l1, inv2 = 1.0f / l2;

    int r1 = qtile * 64 + warp * 16 + (lane >> 2);
    int r2 = r1 + 8;
    int cb = 2 * (lane & 3);
    if (r1 < NQ) {
        float* o1 = out + ((size_t)region * NQ + r1) * CC + cb;
        #pragma unroll
        for (int j = 0; j < 32; j++)
            *(float2*)(o1 + j * 8) = make_float2(acc[j][0] * inv1, acc[j][1] * inv1);
    }
    if (r2 < NQ) {
        float* o2 = out + ((size_t)region * NQ + r2) * CC + cb;
        #pragma unroll
        for (int j = 0; j < 32; j++)
            *(float2*)(o2 + j * 8) = make_float2(acc[j][2] * inv2, acc[j][3] * inv2);
    }
}

// ---------------- positions (second tuple output) ----------------
__global__ void pos_kernel(float* __restrict__ out, int out_size) {
    int t = threadIdx.x;
    if (t < NREG && out_size >= OUT_ELEMS + POS_ELEMS) {
        out[OUT_ELEMS + 2 * t + 0] = (float)(t / GDIM) * (1.0f / 7.0f);
        out[OUT_ELEMS + 2 * t + 1] = (float)(t % GDIM) * (1.0f / 7.0f);
    }
}

extern "C" void kernel_launch(void* const* d_in, const int* in_sizes, int n_in,
                              void* d_out, int out_size) {
    const float* images  = (const float*)d_in[0];
    const float* queries = (const float*)d_in[1];
    if (n_in >= 2 && in_sizes[0] == NQ * CC) {
        const float* t = images; images = queries; queries = t;
    }
    float* out = (float*)d_out;

    cudaFuncSetAttribute(attn_kernel,
                         cudaFuncAttributeMaxDynamicSharedMemorySize, SMEM_BYTES);

    // pos_kernel first so ncu "-s 5 -c 1" lands on attn_kernel
    pos_kernel<<<1, 64>>>(out, out_size);
    attn_kernel<<<196 * 2, THREADS, SMEM_BYTES>>>(images, queries, out);
}

// round 13
// speedup vs baseline: 1.2011x; 1.0514x over previous
#include <cuda_runtime.h>
#include <cuda_bf16.h>
#include <cstdint>

#define NB 4
#define GDIM 7
#define NREG 49
#define HH 224
#define CC 256
#define NQ 100
#define HSTRIDE (HH*CC)
#define THREADS 128
#define NSPLIT 3            // key splits per (region, qtile)
#define NWORK (NREG*NB*2*NSPLIT)   // 1176
#define PAD 264             // bf16 row stride (528B -> conflict-free ldmatrix)

#define OUT_ELEMS (NB*NREG*NQ*CC)
#define POS_ELEMS (NREG*2)

// smem byte offsets
#define SQ_HI 0
#define SQ_LO 33792         // 64*264*2
#define SK_HI 67584
#define SK_LO 84480         // SK_HI + 32*264*2
#define SMEM_BYTES 101376   // 2 CTAs/SM
#define QHILO 33792
#define KHILO 16896

// split-K scratch (device globals: no allocation in kernel_launch)
__device__ float g_opart[(size_t)NWORK * 64 * 256];   // unnormalized partial O
__device__ float g_m[NWORK * 64];
__device__ float g_l[NWORK * 64];

// ---------------- helpers ----------------
__device__ __forceinline__ uint32_t smem_u32(const void* p) {
    uint32_t a;
    asm("{ .reg .u64 t; cvta.to.shared.u64 t, %1; cvt.u32.u64 %0, t; }" : "=r"(a) : "l"(p));
    return a;
}
__device__ __forceinline__ uint32_t cvt2(float a, float b) {  // {lo=a, hi=b}
    uint32_t r; asm("cvt.rn.bf16x2.f32 %0, %2, %1;" : "=r"(r) : "f"(a), "f"(b));
    return r;
}
__device__ __forceinline__ void split2(float a, float b, uint32_t& hi, uint32_t& lo) {
    hi = cvt2(a, b);
    float ah = __uint_as_float(hi << 16);
    float bh = __uint_as_float(hi & 0xFFFF0000u);
    lo = cvt2(a - ah, b - bh);
}
__device__ __forceinline__ void ldsm4(uint32_t r[4], uint32_t a) {
    asm volatile("ldmatrix.sync.aligned.m8n8.x4.shared.b16 {%0,%1,%2,%3}, [%4];"
        : "=r"(r[0]), "=r"(r[1]), "=r"(r[2]), "=r"(r[3]) : "r"(a));
}
__device__ __forceinline__ void ldsm4t(uint32_t r[4], uint32_t a) {
    asm volatile("ldmatrix.sync.aligned.m8n8.x4.trans.shared.b16 {%0,%1,%2,%3}, [%4];"
        : "=r"(r[0]), "=r"(r[1]), "=r"(r[2]), "=r"(r[3]) : "r"(a));
}
__device__ __forceinline__ void mma16816(float* c, const uint32_t* a, uint32_t b0, uint32_t b1) {
    asm volatile("mma.sync.aligned.m16n8k16.row.col.f32.bf16.bf16.f32 "
        "{%0,%1,%2,%3}, {%4,%5,%6,%7}, {%8,%9}, {%0,%1,%2,%3};"
        : "+f"(c[0]), "+f"(c[1]), "+f"(c[2]), "+f"(c[3])
        : "r"(a[0]), "r"(a[1]), "r"(a[2]), "r"(a[3]), "r"(b0), "r"(b1));
}

// ================= main attention kernel =================
// grid = 1176: work = region*6 + qtile*3 + split; 128 threads (4 warps x 16 rows)
// 2 CTAs resident per SM; 3.97 waves (vs 1.32 before split-K)
__global__ void __launch_bounds__(THREADS, 2)
attn_kernel(const float* __restrict__ images,
            const float* __restrict__ queries)
{
    extern __shared__ char smem[];
    const uint32_t sa = smem_u32(smem);

    const int bx     = blockIdx.x;
    const int region = bx / (2 * NSPLIT);
    const int rem    = bx % (2 * NSPLIT);
    const int qtile  = rem / NSPLIT;
    const int split  = rem % NSPLIT;
    const int p0 = split * 11;                    // 0,11,22
    const int p1 = (split == 2) ? 32 : p0 + 11;   // 11,22,32
    const int b  = region / NREG;
    const int n  = region % NREG;
    const int gi = n / GDIM;
    const int gj = n % GDIM;

    const int tid  = threadIdx.x;
    const int lane = tid & 31;
    const int warp = tid >> 5;          // 0..3, rows warp*16..warp*16+15

    // ---- stage Q hi/lo: [64 rows][PAD] bf16 each ----
    for (int id = tid; id < 64 * 128; id += THREADS) {   // channel pairs
        int q = id >> 7;
        int c = (id & 127) * 2;
        int qg = qtile * 64 + q;
        float x = 0.0f, y = 0.0f;
        if (qg < NQ) {
            float2 v = *(const float2*)&queries[qg * CC + c];
            x = v.x; y = v.y;
        }
        uint32_t h, l;
        split2(x, y, h, l);
        uint32_t o = (q * PAD + c) * 2;
        *(uint32_t*)(smem + SQ_HI + o) = h;
        *(uint32_t*)(smem + SQ_LO + o) = l;
    }

    // ---- per-lane ldmatrix base addresses ----
    const uint32_t qA = sa + SQ_HI +
        (((warp * 16) + (lane & 15)) * PAD + (lane >> 4) * 8) * 2;
    const uint32_t kB = sa + SK_HI +
        (((lane & 7) + (lane >> 4) * 8) * PAD + ((lane >> 3) & 1) * 8) * 2;
    const uint32_t vB = sa + SK_HI +
        (((lane & 7) + ((lane >> 3) & 1) * 8) * PAD + (lane >> 4) * 8) * 2;

    const float* imgbase = images + ((size_t)(b * HH + gi * 32) * HH + gj * 32) * CC;

    // ---- state ----
    float acc[32][4];
    #pragma unroll
    for (int j = 0; j < 32; j++)
        #pragma unroll
        for (int k = 0; k < 4; k++) acc[j][k] = 0.0f;
    float m1 = -1e30f, m2 = -1e30f, l1 = 0.0f, l2 = 0.0f;

    for (int p = p0; p < p1; p++) {
        // ---- load 32 keys (one contiguous row-strip) ----
        float4 v[16];
        {
            const float4* g0 = (const float4*)(imgbase + (size_t)p * HSTRIDE);
            #pragma unroll
            for (int it = 0; it < 16; it++) v[it] = g0[tid + it * THREADS];
        }
        __syncthreads();                // prev pass compute done
        #pragma unroll
        for (int it = 0; it < 16; it++) {
            int id = tid + it * THREADS;       // 0..2047
            int s = id >> 6, c4 = id & 63;
            uint32_t h0, l0, h1, l1_;
            split2(v[it].x, v[it].y, h0, l0);
            split2(v[it].z, v[it].w, h1, l1_);
            uint32_t o = (s * PAD + c4 * 4) * 2;
            *(uint2*)(smem + SK_HI + o) = make_uint2(h0, h1);
            *(uint2*)(smem + SK_LO + o) = make_uint2(l0, l1_);
        }
        __syncthreads();

        // ---- QK: S[16 x 32], 3-term bf16 emulation ----
        float s_[4][4];
        #pragma unroll
        for (int j = 0; j < 4; j++)
            #pragma unroll
            for (int k = 0; k < 4; k++) s_[j][k] = 0.0f;

        #pragma unroll
        for (int ks = 0; ks < 16; ks++) {
            uint32_t ah[4], al[4];
            ldsm4(ah, qA + ks * 32);
            ldsm4(al, qA + QHILO + ks * 32);
            #pragma unroll
            for (int j = 0; j < 2; j++) {          // 16 keys per iter
                uint32_t bh[4], bl[4];
                uint32_t ko = kB + j * (16 * PAD * 2) + ks * 32;
                ldsm4(bh, ko);
                ldsm4(bl, ko + KHILO);
                mma16816(s_[2*j],   ah, bh[0], bh[1]);
                mma16816(s_[2*j],   ah, bl[0], bl[1]);
                mma16816(s_[2*j],   al, bh[0], bh[1]);
                mma16816(s_[2*j+1], ah, bh[2], bh[3]);
                mma16816(s_[2*j+1], ah, bl[2], bl[3]);
                mma16816(s_[2*j+1], al, bh[2], bh[3]);
            }
        }

        // ---- online softmax (rows r=lane>>2 and r+8) ----
        float mx1 = -1e30f, mx2 = -1e30f;
        #pragma unroll
        for (int j = 0; j < 4; j++) {
            mx1 = fmaxf(mx1, fmaxf(s_[j][0], s_[j][1]));
            mx2 = fmaxf(mx2, fmaxf(s_[j][2], s_[j][3]));
        }
        mx1 = fmaxf(mx1, __shfl_xor_sync(0xffffffffu, mx1, 1));
        mx1 = fmaxf(mx1, __shfl_xor_sync(0xffffffffu, mx1, 2));
        mx2 = fmaxf(mx2, __shfl_xor_sync(0xffffffffu, mx2, 1));
        mx2 = fmaxf(mx2, __shfl_xor_sync(0xffffffffu, mx2, 2));
        float m1n = fmaxf(m1, mx1), m2n = fmaxf(m2, mx2);
        float a1 = __expf(m1 - m1n), a2 = __expf(m2 - m2n);
        m1 = m1n; m2 = m2n;

        float sum1 = 0.0f, sum2 = 0.0f;
        #pragma unroll
        for (int j = 0; j < 4; j++) {
            s_[j][0] = __expf(s_[j][0] - m1); sum1 += s_[j][0];
            s_[j][1] = __expf(s_[j][1] - m1); sum1 += s_[j][1];
            s_[j][2] = __expf(s_[j][2] - m2); sum2 += s_[j][2];
            s_[j][3] = __expf(s_[j][3] - m2); sum2 += s_[j][3];
        }
        l1 = l1 * a1 + sum1;
        l2 = l2 * a2 + sum2;

        // skip rescale when max didn't move (warp-uniform branch)
        if (!__all_sync(0xffffffffu, (a1 == 1.0f) && (a2 == 1.0f))) {
            #pragma unroll
            for (int j = 0; j < 32; j++) {
                acc[j][0] *= a1; acc[j][1] *= a1;
                acc[j][2] *= a2; acc[j][3] *= a2;
            }
        }

        // ---- pack P into PV A-fragments (C->A layout identity) ----
        uint32_t pAh[2][4], pAl[2][4];
        #pragma unroll
        for (int kk = 0; kk < 2; kk++) {
            split2(s_[2*kk][0],   s_[2*kk][1],   pAh[kk][0], pAl[kk][0]);
            split2(s_[2*kk][2],   s_[2*kk][3],   pAh[kk][1], pAl[kk][1]);
            split2(s_[2*kk+1][0], s_[2*kk+1][1], pAh[kk][2], pAl[kk][2]);
            split2(s_[2*kk+1][2], s_[2*kk+1][3], pAh[kk][3], pAl[kk][3]);
        }

        // ---- PV: O += P[16x32] * V[32x256], 3-term ----
        #pragma unroll
        for (int nn = 0; nn < 16; nn++) {
            #pragma unroll
            for (int kk = 0; kk < 2; kk++) {
                uint32_t bh[4], bl[4];
                uint32_t vo = vB + (kk * 16 * PAD + nn * 16) * 2;
                ldsm4t(bh, vo);
                ldsm4t(bl, vo + KHILO);
                mma16816(acc[2*nn],   pAh[kk], bh[0], bh[1]);
                mma16816(acc[2*nn],   pAh[kk], bl[0], bl[1]);
                mma16816(acc[2*nn],   pAl[kk], bh[0], bh[1]);
                mma16816(acc[2*nn+1], pAh[kk], bh[2], bh[3]);
                mma16816(acc[2*nn+1], pAh[kk], bl[2], bl[3]);
                mma16816(acc[2*nn+1], pAl[kk], bh[2], bh[3]);
            }
        }
    }

    // ---- epilogue: store UNNORMALIZED partials + (m, l) ----
    l1 += __shfl_xor_sync(0xffffffffu, l1, 1);
    l1 += __shfl_xor_sync(0xffffffffu, l1, 2);
    l2 += __shfl_xor_sync(0xffffffffu, l2, 1);
    l2 += __shfl_xor_sync(0xffffffffu, l2, 2);

    int r1 = warp * 16 + (lane >> 2);   // local row 0..63
    int r2 = r1 + 8;
    int cb = 2 * (lane & 3);
    float* o1 = g_opart + ((size_t)bx * 64 + r1) * 256 + cb;
    float* o2 = g_opart + ((size_t)bx * 64 + r2) * 256 + cb;
    #pragma unroll
    for (int j = 0; j < 32; j++) {
        *(float2*)(o1 + j * 8) = make_float2(acc[j][0], acc[j][1]);
        *(float2*)(o2 + j * 8) = make_float2(acc[j][2], acc[j][3]);
    }
    if ((lane & 3) == 0) {
        g_m[bx * 64 + r1] = m1;  g_l[bx * 64 + r1] = l1;
        g_m[bx * 64 + r2] = m2;  g_l[bx * 64 + r2] = l2;
    }
}

// ================= combine kernel =================
// grid = 392 (region*2 + qtile), 256 threads
__global__ void __launch_bounds__(256)
combine_kernel(float* __restrict__ out)
{
    __shared__ float sc[NSPLIT][64];
    const int cta = blockIdx.x;
    const int region = cta >> 1;
    const int qtile  = cta & 1;
    const int base   = cta * NSPLIT;
    const int t = threadIdx.x;

    if (t < 64) {
        float m0 = g_m[(base + 0) * 64 + t];
        float m1 = g_m[(base + 1) * 64 + t];
        float m2 = g_m[(base + 2) * 64 + t];
        float M  = fmaxf(m0, fmaxf(m1, m2));
        float e0 = __expf(m0 - M), e1 = __expf(m1 - M), e2 = __expf(m2 - M);
        float den = g_l[(base + 0) * 64 + t] * e0
                  + g_l[(base + 1) * 64 + t] * e1
                  + g_l[(base + 2) * 64 + t] * e2;
        float inv = 1.0f / den;
        sc[0][t] = e0 * inv;  sc[1][t] = e1 * inv;  sc[2][t] = e2 * inv;
    }
    __syncthreads();

    // 64 rows x 64 float4 = 4096 float4; 16 per thread
    for (int i = t; i < 4096; i += 256) {
        int row = i >> 6;
        int c4  = i & 63;
        size_t off = ((size_t)base * 64 + row) * 256 + c4 * 4;
        float4 a = *(const float4*)&g_opart[off];
        float4 bq = *(const float4*)&g_opart[off + (size_t)64 * 256];
        float4 c = *(const float4*)&g_opart[off + (size_t)2 * 64 * 256];
        float s0 = sc[0][row], s1 = sc[1][row], s2 = sc[2][row];
        int qg = qtile * 64 + row;
        if (qg < NQ) {
            float4 r;
            r.x = a.x * s0 + bq.x * s1 + c.x * s2;
            r.y = a.y * s0 + bq.y * s1 + c.y * s2;
            r.z = a.z * s0 + bq.z * s1 + c.z * s2;
            r.w = a.w * s0 + bq.w * s1 + c.w * s2;
            *(float4*)&out[((size_t)region * NQ + qg) * CC + c4 * 4] = r;
        }
    }
}

// ---------------- positions (second tuple output) ----------------
__global__ void pos_kernel(float* __restrict__ out, int out_size) {
    int t = threadIdx.x;
    if (t < NREG && out_size >= OUT_ELEMS + POS_ELEMS) {
        out[OUT_ELEMS + 2 * t + 0] = (float)(t / GDIM) * (1.0f / 7.0f);
        out[OUT_ELEMS + 2 * t + 1] = (float)(t % GDIM) * (1.0f / 7.0f);
    }
}

extern "C" void kernel_launch(void* const* d_in, const int* in_sizes, int n_in,
                              void* d_out, int out_size) {
    const float* images  = (const float*)d_in[0];
    const float* queries = (const float*)d_in[1];
    if (n_in >= 2 && in_sizes[0] == NQ * CC) {
        const float* t = images; images = queries; queries = t;
    }
    float* out = (float*)d_out;

    cudaFuncSetAttribute(attn_kernel,
                         cudaFuncAttributeMaxDynamicSharedMemorySize, SMEM_BYTES);

    // 4-launch cycle keeps attn_kernel at ncu's "-s 5 -c 1" slot (launch #6)
    pos_kernel<<<1, 64>>>(out, out_size);
    attn_kernel<<<NWORK, THREADS, SMEM_BYTES>>>(images, queries);
    combine_kernel<<<NREG * NB * 2, 256>>>(out);
    pos_kernel<<<1, 64>>>(out, out_size);
}

// round 14
// speedup vs baseline: 1.4270x; 1.1880x over previous
#include <cuda_runtime.h>
#include <cuda_fp16.h>
#include <cstdint>

#define NB 4
#define GDIM 7
#define NREG 49
#define HH 224
#define CC 256
#define NQ 100
#define HSTRIDE (HH*CC)
#define THREADS 128
#define NSPLIT 3            // key splits per (region, qtile)
#define NWORK (NREG*NB*2*NSPLIT)   // 1176
#define PAD 264             // fp16 row stride (528B -> conflict-free ldmatrix)

#define OUT_ELEMS (NB*NREG*NQ*CC)
#define POS_ELEMS (NREG*2)

// smem byte offsets
#define SQ_HI 0
#define SQ_LO 33792         // 64*264*2
#define SK_HI 67584
#define SK_LO 84480         // SK_HI + 32*264*2
#define SMEM_BYTES 101376   // 2 CTAs/SM
#define QHILO 33792
#define KHILO 16896

// split-K scratch (device globals: no allocation in kernel_launch)
__device__ float g_opart[(size_t)NWORK * 64 * 256];   // unnormalized partial O
__device__ float g_m[NWORK * 64];
__device__ float g_l[NWORK * 64];

// ---------------- helpers ----------------
__device__ __forceinline__ uint32_t smem_u32(const void* p) {
    uint32_t a;
    asm("{ .reg .u64 t; cvta.to.shared.u64 t, %1; cvt.u32.u64 %0, t; }" : "=r"(a) : "l"(p));
    return a;
}
__device__ __forceinline__ uint32_t cvt2h(float a, float b) {  // pack {lo=a, hi=b} fp16x2
    uint32_t r; asm("cvt.rn.f16x2.f32 %0, %2, %1;" : "=r"(r) : "f"(a), "f"(b));
    return r;
}
// fp16 hi/lo split: x = hi + lo with |lo| <= 2^-12 |x|
__device__ __forceinline__ void split2h(float a, float b, uint32_t& hi, uint32_t& lo) {
    hi = cvt2h(a, b);
    __half2 hh = *reinterpret_cast<__half2*>(&hi);
    float2 f = __half22float2(hh);        // f.x <-> a (lower), f.y <-> b (upper)
    lo = cvt2h(a - f.x, b - f.y);
}
__device__ __forceinline__ void ldsm4(uint32_t r[4], uint32_t a) {
    asm volatile("ldmatrix.sync.aligned.m8n8.x4.shared.b16 {%0,%1,%2,%3}, [%4];"
        : "=r"(r[0]), "=r"(r[1]), "=r"(r[2]), "=r"(r[3]) : "r"(a));
}
__device__ __forceinline__ void ldsm4t(uint32_t r[4], uint32_t a) {
    asm volatile("ldmatrix.sync.aligned.m8n8.x4.trans.shared.b16 {%0,%1,%2,%3}, [%4];"
        : "=r"(r[0]), "=r"(r[1]), "=r"(r[2]), "=r"(r[3]) : "r"(a));
}
__device__ __forceinline__ void mma16816(float* c, const uint32_t* a, uint32_t b0, uint32_t b1) {
    asm volatile("mma.sync.aligned.m16n8k16.row.col.f32.f16.f16.f32 "
        "{%0,%1,%2,%3}, {%4,%5,%6,%7}, {%8,%9}, {%0,%1,%2,%3};"
        : "+f"(c[0]), "+f"(c[1]), "+f"(c[2]), "+f"(c[3])
        : "r"(a[0]), "r"(a[1]), "r"(a[2]), "r"(a[3]), "r"(b0), "r"(b1));
}

// ================= main attention kernel =================
// grid = 1176: work = region*6 + qtile*3 + split; 128 threads (4 warps x 16 rows)
// 2 CTAs resident per SM; ~4 waves
__global__ void __launch_bounds__(THREADS, 2)
attn_kernel(const float* __restrict__ images,
            const float* __restrict__ queries)
{
    extern __shared__ char smem[];
    const uint32_t sa = smem_u32(smem);

    const int bx     = blockIdx.x;
    const int region = bx / (2 * NSPLIT);
    const int rem    = bx % (2 * NSPLIT);
    const int qtile  = rem / NSPLIT;
    const int split  = rem % NSPLIT;
    const int p0 = split * 11;                    // 0,11,22
    const int p1 = (split == 2) ? 32 : p0 + 11;   // 11,22,32
    const int b  = region / NREG;
    const int n  = region % NREG;
    const int gi = n / GDIM;
    const int gj = n % GDIM;

    const int tid  = threadIdx.x;
    const int lane = tid & 31;
    const int warp = tid >> 5;          // 0..3, rows warp*16..warp*16+15

    // ---- stage Q hi/lo: [64 rows][PAD] fp16 each ----
    for (int id = tid; id < 64 * 128; id += THREADS) {   // channel pairs
        int q = id >> 7;
        int c = (id & 127) * 2;
        int qg = qtile * 64 + q;
        float x = 0.0f, y = 0.0f;
        if (qg < NQ) {
            float2 v = *(const float2*)&queries[qg * CC + c];
            x = v.x; y = v.y;
        }
        uint32_t h, l;
        split2h(x, y, h, l);
        uint32_t o = (q * PAD + c) * 2;
        *(uint32_t*)(smem + SQ_HI + o) = h;
        *(uint32_t*)(smem + SQ_LO + o) = l;
    }

    // ---- per-lane ldmatrix base addresses ----
    const uint32_t qA = sa + SQ_HI +
        (((warp * 16) + (lane & 15)) * PAD + (lane >> 4) * 8) * 2;
    const uint32_t kB = sa + SK_HI +
        (((lane & 7) + (lane >> 4) * 8) * PAD + ((lane >> 3) & 1) * 8) * 2;
    const uint32_t vB = sa + SK_HI +
        (((lane & 7) + ((lane >> 3) & 1) * 8) * PAD + (lane >> 4) * 8) * 2;

    const float* imgbase = images + ((size_t)(b * HH + gi * 32) * HH + gj * 32) * CC;

    // ---- state ----
    float acc[32][4];
    #pragma unroll
    for (int j = 0; j < 32; j++)
        #pragma unroll
        for (int k = 0; k < 4; k++) acc[j][k] = 0.0f;
    float m1 = -1e30f, m2 = -1e30f, l1 = 0.0f, l2 = 0.0f;

    for (int p = p0; p < p1; p++) {
        // ---- load 32 keys (one contiguous row-strip) ----
        float4 v[16];
        {
            const float4* g0 = (const float4*)(imgbase + (size_t)p * HSTRIDE);
            #pragma unroll
            for (int it = 0; it < 16; it++) v[it] = g0[tid + it * THREADS];
        }
        __syncthreads();                // prev pass compute done
        #pragma unroll
        for (int it = 0; it < 16; it++) {
            int id = tid + it * THREADS;       // 0..2047
            int s = id >> 6, c4 = id & 63;
            uint32_t h0, l0, h1, l1_;
            split2h(v[it].x, v[it].y, h0, l0);
            split2h(v[it].z, v[it].w, h1, l1_);
            uint32_t o = (s * PAD + c4 * 4) * 2;
            *(uint2*)(smem + SK_HI + o) = make_uint2(h0, h1);
            *(uint2*)(smem + SK_LO + o) = make_uint2(l0, l1_);
        }
        __syncthreads();

        // ---- QK: S[16 x 32], 3-term fp16 emulation (err ~2^-24) ----
        float s_[4][4];
        #pragma unroll
        for (int j = 0; j < 4; j++)
            #pragma unroll
            for (int k = 0; k < 4; k++) s_[j][k] = 0.0f;

        #pragma unroll
        for (int ks = 0; ks < 16; ks++) {
            uint32_t ah[4], al[4];
            ldsm4(ah, qA + ks * 32);
            ldsm4(al, qA + QHILO + ks * 32);
            #pragma unroll
            for (int j = 0; j < 2; j++) {          // 16 keys per iter
                uint32_t bh[4], bl[4];
                uint32_t ko = kB + j * (16 * PAD * 2) + ks * 32;
                ldsm4(bh, ko);
                ldsm4(bl, ko + KHILO);
                mma16816(s_[2*j],   ah, bh[0], bh[1]);
                mma16816(s_[2*j],   ah, bl[0], bl[1]);
                mma16816(s_[2*j],   al, bh[0], bh[1]);
                mma16816(s_[2*j+1], ah, bh[2], bh[3]);
                mma16816(s_[2*j+1], ah, bl[2], bl[3]);
                mma16816(s_[2*j+1], al, bh[2], bh[3]);
            }
        }

        // ---- online softmax (rows r=lane>>2 and r+8) ----
        float mx1 = -1e30f, mx2 = -1e30f;
        #pragma unroll
        for (int j = 0; j < 4; j++) {
            mx1 = fmaxf(mx1, fmaxf(s_[j][0], s_[j][1]));
            mx2 = fmaxf(mx2, fmaxf(s_[j][2], s_[j][3]));
        }
        mx1 = fmaxf(mx1, __shfl_xor_sync(0xffffffffu, mx1, 1));
        mx1 = fmaxf(mx1, __shfl_xor_sync(0xffffffffu, mx1, 2));
        mx2 = fmaxf(mx2, __shfl_xor_sync(0xffffffffu, mx2, 1));
        mx2 = fmaxf(mx2, __shfl_xor_sync(0xffffffffu, mx2, 2));
        float m1n = fmaxf(m1, mx1), m2n = fmaxf(m2, mx2);
        float a1 = __expf(m1 - m1n), a2 = __expf(m2 - m2n);
        m1 = m1n; m2 = m2n;

        float sum1 = 0.0f, sum2 = 0.0f;
        #pragma unroll
        for (int j = 0; j < 4; j++) {
            s_[j][0] = __expf(s_[j][0] - m1); sum1 += s_[j][0];
            s_[j][1] = __expf(s_[j][1] - m1); sum1 += s_[j][1];
            s_[j][2] = __expf(s_[j][2] - m2); sum2 += s_[j][2];
            s_[j][3] = __expf(s_[j][3] - m2); sum2 += s_[j][3];
        }
        l1 = l1 * a1 + sum1;
        l2 = l2 * a2 + sum2;

        // skip rescale when max didn't move (warp-uniform branch)
        if (!__all_sync(0xffffffffu, (a1 == 1.0f) && (a2 == 1.0f))) {
            #pragma unroll
            for (int j = 0; j < 32; j++) {
                acc[j][0] *= a1; acc[j][1] *= a1;
                acc[j][2] *= a2; acc[j][3] *= a2;
            }
        }

        // ---- pack P into PV A-fragments: single fp16 (1-term PV) ----
        uint32_t pAh[2][4];
        #pragma unroll
        for (int kk = 0; kk < 2; kk++) {
            pAh[kk][0] = cvt2h(s_[2*kk][0],   s_[2*kk][1]);
            pAh[kk][1] = cvt2h(s_[2*kk][2],   s_[2*kk][3]);
            pAh[kk][2] = cvt2h(s_[2*kk+1][0], s_[2*kk+1][1]);
            pAh[kk][3] = cvt2h(s_[2*kk+1][2], s_[2*kk+1][3]);
        }

        // ---- PV: O += P[16x32] * V[32x256], 1-term fp16 ----
        #pragma unroll
        for (int nn = 0; nn < 16; nn++) {
            #pragma unroll
            for (int kk = 0; kk < 2; kk++) {
                uint32_t bh[4];
                ldsm4t(bh, vB + (kk * 16 * PAD + nn * 16) * 2);
                mma16816(acc[2*nn],   pAh[kk], bh[0], bh[1]);
                mma16816(acc[2*nn+1], pAh[kk], bh[2], bh[3]);
            }
        }
    }

    // ---- epilogue: store UNNORMALIZED partials + (m, l) ----
    l1 += __shfl_xor_sync(0xffffffffu, l1, 1);
    l1 += __shfl_xor_sync(0xffffffffu, l1, 2);
    l2 += __shfl_xor_sync(0xffffffffu, l2, 1);
    l2 += __shfl_xor_sync(0xffffffffu, l2, 2);

    int r1 = warp * 16 + (lane >> 2);   // local row 0..63
    int r2 = r1 + 8;
    int cb = 2 * (lane & 3);
    float* o1 = g_opart + ((size_t)bx * 64 + r1) * 256 + cb;
    float* o2 = g_opart + ((size_t)bx * 64 + r2) * 256 + cb;
    #pragma unroll
    for (int j = 0; j < 32; j++) {
        *(float2*)(o1 + j * 8) = make_float2(acc[j][0], acc[j][1]);
        *(float2*)(o2 + j * 8) = make_float2(acc[j][2], acc[j][3]);
    }
    if ((lane & 3) == 0) {
        g_m[bx * 64 + r1] = m1;  g_l[bx * 64 + r1] = l1;
        g_m[bx * 64 + r2] = m2;  g_l[bx * 64 + r2] = l2;
    }
}

// ================= combine kernel =================
// grid = 392 (region*2 + qtile), 256 threads
__global__ void __launch_bounds__(256)
combine_kernel(float* __restrict__ out)
{
    __shared__ float sc[NSPLIT][64];
    const int cta = blockIdx.x;
    const int region = cta >> 1;
    const int qtile  = cta & 1;
    const int base   = cta * NSPLIT;
    const int t = threadIdx.x;

    if (t < 64) {
        float m0 = g_m[(base + 0) * 64 + t];
        float m1 = g_m[(base + 1) * 64 + t];
        float m2 = g_m[(base + 2) * 64 + t];
        float M  = fmaxf(m0, fmaxf(m1, m2));
        float e0 = __expf(m0 - M), e1 = __expf(m1 - M), e2 = __expf(m2 - M);
        float den = g_l[(base + 0) * 64 + t] * e0
                  + g_l[(base + 1) * 64 + t] * e1
                  + g_l[(base + 2) * 64 + t] * e2;
        float inv = 1.0f / den;
        sc[0][t] = e0 * inv;  sc[1][t] = e1 * inv;  sc[2][t] = e2 * inv;
    }
    __syncthreads();

    // 64 rows x 64 float4 = 4096 float4; 16 per thread
    for (int i = t; i < 4096; i += 256) {
        int row = i >> 6;
        int c4  = i & 63;
        size_t off = ((size_t)base * 64 + row) * 256 + c4 * 4;
        float4 a = *(const float4*)&g_opart[off];
        float4 bq = *(const float4*)&g_opart[off + (size_t)64 * 256];
        float4 c = *(const float4*)&g_opart[off + (size_t)2 * 64 * 256];
        float s0 = sc[0][row], s1 = sc[1][row], s2 = sc[2][row];
        int qg = qtile * 64 + row;
        if (qg < NQ) {
            float4 r;
            r.x = a.x * s0 + bq.x * s1 + c.x * s2;
            r.y = a.y * s0 + bq.y * s1 + c.y * s2;
            r.z = a.z * s0 + bq.z * s1 + c.z * s2;
            r.w = a.w * s0 + bq.w * s1 + c.w * s2;
            *(float4*)&out[((size_t)region * NQ + qg) * CC + c4 * 4] = r;
        }
    }
}

// ---------------- positions (second tuple output) ----------------
__global__ void pos_kernel(float* __restrict__ out, int out_size) {
    int t = threadIdx.x;
    if (t < NREG && out_size >= OUT_ELEMS + POS_ELEMS) {
        out[OUT_ELEMS + 2 * t + 0] = (float)(t / GDIM) * (1.0f / 7.0f);
        out[OUT_ELEMS + 2 * t + 1] = (float)(t % GDIM) * (1.0f / 7.0f);
    }
}

extern "C" void kernel_launch(void* const* d_in, const int* in_sizes, int n_in,
                              void* d_out, int out_size) {
    const float* images  = (const float*)d_in[0];
    const float* queries = (const float*)d_in[1];
    if (n_in >= 2 && in_sizes[0] == NQ * CC) {
        const float* t = images; images = queries; queries = t;
    }
    float* out = (float*)d_out;

    cudaFuncSetAttribute(attn_kernel,
                         cudaFuncAttributeMaxDynamicSharedMemorySize, SMEM_BYTES);

    pos_kernel<<<1, 64>>>(out, out_size);
    attn_kernel<<<NWORK, THREADS, SMEM_BYTES>>>(images, queries);
    combine_kernel<<<NREG * NB * 2, 256>>>(out);
    pos_kernel<<<1, 64>>>(out, out_size);
}

// round 15
// speedup vs baseline: 1.4319x; 1.0034x over previous
#include <cuda_runtime.h>
#include <cuda_fp16.h>
#include <cstdint>

#define NB 4
#define GDIM 7
#define NREG 49
#define HH 224
#define CC 256
#define NQ 100
#define HSTRIDE (HH*CC)
#define THREADS 128
#define NSPLIT 3            // key splits per (region, qtile)
#define NWORK (NREG*NB*2*NSPLIT)   // 1176
#define PAD 264             // fp16 row stride (528B -> conflict-free ldmatrix)

#define OUT_ELEMS (NB*NREG*NQ*CC)
#define POS_ELEMS (NREG*2)

// smem byte offsets
#define SQ_HI 0
#define SQ_LO 33792         // 64*264*2
#define SK_HI 67584
#define SK_LO 84480         // SK_HI + 32*264*2
#define SMEM_BYTES 101376   // 2 CTAs/SM
#define QHILO 33792
#define KHILO 16896

// split-K scratch (device globals: no allocation in kernel_launch)
__device__ float g_opart[(size_t)NWORK * 64 * 256];   // unnormalized partial O
__device__ float g_m[NWORK * 64];
__device__ float g_l[NWORK * 64];

// ---------------- helpers ----------------
__device__ __forceinline__ uint32_t smem_u32(const void* p) {
    uint32_t a;
    asm("{ .reg .u64 t; cvta.to.shared.u64 t, %1; cvt.u32.u64 %0, t; }" : "=r"(a) : "l"(p));
    return a;
}
__device__ __forceinline__ uint32_t cvt2h(float a, float b) {  // pack {lo=a, hi=b} fp16x2
    uint32_t r; asm("cvt.rn.f16x2.f32 %0, %2, %1;" : "=r"(r) : "f"(a), "f"(b));
    return r;
}
// fp16 hi/lo split: x = hi + lo with |lo| <= 2^-12 |x|
__device__ __forceinline__ void split2h(float a, float b, uint32_t& hi, uint32_t& lo) {
    hi = cvt2h(a, b);
    __half2 hh = *reinterpret_cast<__half2*>(&hi);
    float2 f = __half22float2(hh);
    lo = cvt2h(a - f.x, b - f.y);
}
__device__ __forceinline__ void ldsm4(uint32_t r[4], uint32_t a) {
    asm volatile("ldmatrix.sync.aligned.m8n8.x4.shared.b16 {%0,%1,%2,%3}, [%4];"
        : "=r"(r[0]), "=r"(r[1]), "=r"(r[2]), "=r"(r[3]) : "r"(a));
}
__device__ __forceinline__ void ldsm4t(uint32_t r[4], uint32_t a) {
    asm volatile("ldmatrix.sync.aligned.m8n8.x4.trans.shared.b16 {%0,%1,%2,%3}, [%4];"
        : "=r"(r[0]), "=r"(r[1]), "=r"(r[2]), "=r"(r[3]) : "r"(a));
}
// f32-accumulate fp16 MMA
__device__ __forceinline__ void mma16816(float* c, const uint32_t* a, uint32_t b0, uint32_t b1) {
    asm volatile("mma.sync.aligned.m16n8k16.row.col.f32.f16.f16.f32 "
        "{%0,%1,%2,%3}, {%4,%5,%6,%7}, {%8,%9}, {%0,%1,%2,%3};"
        : "+f"(c[0]), "+f"(c[1]), "+f"(c[2]), "+f"(c[3])
        : "r"(a[0]), "r"(a[1]), "r"(a[2]), "r"(a[3]), "r"(b0), "r"(b1));
}
// f16-accumulate fp16 MMA (for tiny cross terms; potentially 2x rate)
__device__ __forceinline__ void mma16816h(uint32_t* c, const uint32_t* a, uint32_t b0, uint32_t b1) {
    asm volatile("mma.sync.aligned.m16n8k16.row.col.f16.f16.f16.f16 "
        "{%0,%1}, {%2,%3,%4,%5}, {%6,%7}, {%0,%1};"
        : "+r"(c[0]), "+r"(c[1])
        : "r"(a[0]), "r"(a[1]), "r"(a[2]), "r"(a[3]), "r"(b0), "r"(b1));
}

// ================= main attention kernel =================
// grid = 1176: work = region*6 + qtile*3 + split; 128 threads (4 warps x 16 rows)
// 2 CTAs resident per SM; ~4 waves
__global__ void __launch_bounds__(THREADS, 2)
attn_kernel(const float* __restrict__ images,
            const float* __restrict__ queries)
{
    extern __shared__ char smem[];
    const uint32_t sa = smem_u32(smem);

    const int bx     = blockIdx.x;
    const int region = bx / (2 * NSPLIT);
    const int rem    = bx % (2 * NSPLIT);
    const int qtile  = rem / NSPLIT;
    const int split  = rem % NSPLIT;
    const int p0 = split * 11;                    // 0,11,22
    const int p1 = (split == 2) ? 32 : p0 + 11;   // 11,22,32
    const int b  = region / NREG;
    const int n  = region % NREG;
    const int gi = n / GDIM;
    const int gj = n % GDIM;

    const int tid  = threadIdx.x;
    const int lane = tid & 31;
    const int warp = tid >> 5;          // 0..3, rows warp*16..warp*16+15

    // ---- stage Q hi/lo: [64 rows][PAD] fp16 each ----
    for (int id = tid; id < 64 * 128; id += THREADS) {   // channel pairs
        int q = id >> 7;
        int c = (id & 127) * 2;
        int qg = qtile * 64 + q;
        float x = 0.0f, y = 0.0f;
        if (qg < NQ) {
            float2 v = *(const float2*)&queries[qg * CC + c];
            x = v.x; y = v.y;
        }
        uint32_t h, l;
        split2h(x, y, h, l);
        uint32_t o = (q * PAD + c) * 2;
        *(uint32_t*)(smem + SQ_HI + o) = h;
        *(uint32_t*)(smem + SQ_LO + o) = l;
    }

    // ---- per-lane ldmatrix base addresses ----
    const uint32_t qA = sa + SQ_HI +
        (((warp * 16) + (lane & 15)) * PAD + (lane >> 4) * 8) * 2;
    const uint32_t kB = sa + SK_HI +
        (((lane & 7) + (lane >> 4) * 8) * PAD + ((lane >> 3) & 1) * 8) * 2;
    const uint32_t vB = sa + SK_HI +
        (((lane & 7) + ((lane >> 3) & 1) * 8) * PAD + (lane >> 4) * 8) * 2;

    const float* imgbase = images + ((size_t)(b * HH + gi * 32) * HH + gj * 32) * CC;

    // ---- state ----
    float acc[32][4];
    #pragma unroll
    for (int j = 0; j < 32; j++)
        #pragma unroll
        for (int k = 0; k < 4; k++) acc[j][k] = 0.0f;
    float m1 = -1e30f, m2 = -1e30f, l1 = 0.0f, l2 = 0.0f;

    for (int p = p0; p < p1; p++) {
        // ---- load 32 keys (one contiguous row-strip) ----
        float4 v[16];
        {
            const float4* g0 = (const float4*)(imgbase + (size_t)p * HSTRIDE);
            #pragma unroll
            for (int it = 0; it < 16; it++) v[it] = g0[tid + it * THREADS];
        }
        __syncthreads();                // prev pass compute done
        #pragma unroll
        for (int it = 0; it < 16; it++) {
            int id = tid + it * THREADS;       // 0..2047
            int s = id >> 6, c4 = id & 63;
            uint32_t h0, l0, h1, l1_;
            split2h(v[it].x, v[it].y, h0, l0);
            split2h(v[it].z, v[it].w, h1, l1_);
            uint32_t o = (s * PAD + c4 * 4) * 2;
            *(uint2*)(smem + SK_HI + o) = make_uint2(h0, h1);
            *(uint2*)(smem + SK_LO + o) = make_uint2(l0, l1_);
        }
        __syncthreads();

        // ---- QK: S[16 x 32]; hh in f32-acc, cross terms in f16-acc ----
        float shh[4][4];
        uint32_t chl[4][2], clh[4][2];
        #pragma unroll
        for (int j = 0; j < 4; j++) {
            #pragma unroll
            for (int k = 0; k < 4; k++) shh[j][k] = 0.0f;
            chl[j][0] = chl[j][1] = 0u;
            clh[j][0] = clh[j][1] = 0u;
        }

        #pragma unroll
        for (int ks = 0; ks < 16; ks++) {
            uint32_t ah[4], al[4];
            ldsm4(ah, qA + ks * 32);
            ldsm4(al, qA + QHILO + ks * 32);
            #pragma unroll
            for (int j = 0; j < 2; j++) {          // 16 keys per iter
                uint32_t bh[4], bl[4];
                uint32_t ko = kB + j * (16 * PAD * 2) + ks * 32;
                ldsm4(bh, ko);
                ldsm4(bl, ko + KHILO);
                mma16816(shh[2*j],    ah, bh[0], bh[1]);
                mma16816(shh[2*j+1],  ah, bh[2], bh[3]);
                mma16816h(chl[2*j],   ah, bl[0], bl[1]);
                mma16816h(chl[2*j+1], ah, bl[2], bl[3]);
                mma16816h(clh[2*j],   al, bh[0], bh[1]);
                mma16816h(clh[2*j+1], al, bh[2], bh[3]);
            }
        }

        // merge: s = hh + hl + lh
        float s_[4][4];
        #pragma unroll
        for (int j = 0; j < 4; j++) {
            float2 c0 = __half22float2(*reinterpret_cast<__half2*>(&chl[j][0]));
            float2 c1 = __half22float2(*reinterpret_cast<__half2*>(&chl[j][1]));
            float2 d0 = __half22float2(*reinterpret_cast<__half2*>(&clh[j][0]));
            float2 d1 = __half22float2(*reinterpret_cast<__half2*>(&clh[j][1]));
            s_[j][0] = shh[j][0] + c0.x + d0.x;
            s_[j][1] = shh[j][1] + c0.y + d0.y;
            s_[j][2] = shh[j][2] + c1.x + d1.x;
            s_[j][3] = shh[j][3] + c1.y + d1.y;
        }

        // ---- online softmax (rows r=lane>>2 and r+8) ----
        float mx1 = -1e30f, mx2 = -1e30f;
        #pragma unroll
        for (int j = 0; j < 4; j++) {
            mx1 = fmaxf(mx1, fmaxf(s_[j][0], s_[j][1]));
            mx2 = fmaxf(mx2, fmaxf(s_[j][2], s_[j][3]));
        }
        mx1 = fmaxf(mx1, __shfl_xor_sync(0xffffffffu, mx1, 1));
        mx1 = fmaxf(mx1, __shfl_xor_sync(0xffffffffu, mx1, 2));
        mx2 = fmaxf(mx2, __shfl_xor_sync(0xffffffffu, mx2, 1));
        mx2 = fmaxf(mx2, __shfl_xor_sync(0xffffffffu, mx2, 2));
        float m1n = fmaxf(m1, mx1), m2n = fmaxf(m2, mx2);
        float a1 = __expf(m1 - m1n), a2 = __expf(m2 - m2n);
        m1 = m1n; m2 = m2n;

        float sum1 = 0.0f, sum2 = 0.0f;
        #pragma unroll
        for (int j = 0; j < 4; j++) {
            s_[j][0] = __expf(s_[j][0] - m1); sum1 += s_[j][0];
            s_[j][1] = __expf(s_[j][1] - m1); sum1 += s_[j][1];
            s_[j][2] = __expf(s_[j][2] - m2); sum2 += s_[j][2];
            s_[j][3] = __expf(s_[j][3] - m2); sum2 += s_[j][3];
        }
        l1 = l1 * a1 + sum1;
        l2 = l2 * a2 + sum2;

        // skip rescale when max didn't move (warp-uniform branch)
        if (!__all_sync(0xffffffffu, (a1 == 1.0f) && (a2 == 1.0f))) {
            #pragma unroll
            for (int j = 0; j < 32; j++) {
                acc[j][0] *= a1; acc[j][1] *= a1;
                acc[j][2] *= a2; acc[j][3] *= a2;
            }
        }

        // ---- pack P into PV A-fragments: single fp16 (1-term PV) ----
        uint32_t pAh[2][4];
        #pragma unroll
        for (int kk = 0; kk < 2; kk++) {
            pAh[kk][0] = cvt2h(s_[2*kk][0],   s_[2*kk][1]);
            pAh[kk][1] = cvt2h(s_[2*kk][2],   s_[2*kk][3]);
            pAh[kk][2] = cvt2h(s_[2*kk+1][0], s_[2*kk+1][1]);
            pAh[kk][3] = cvt2h(s_[2*kk+1][2], s_[2*kk+1][3]);
        }

        // ---- PV: O += P[16x32] * V[32x256], 1-term fp16, f32 acc ----
        #pragma unroll
        for (int nn = 0; nn < 16; nn++) {
            #pragma unroll
            for (int kk = 0; kk < 2; kk++) {
                uint32_t bh[4];
                ldsm4t(bh, vB + (kk * 16 * PAD + nn * 16) * 2);
                mma16816(acc[2*nn],   pAh[kk], bh[0], bh[1]);
                mma16816(acc[2*nn+1], pAh[kk], bh[2], bh[3]);
            }
        }
    }

    // ---- epilogue: store UNNORMALIZED partials + (m, l) ----
    l1 += __shfl_xor_sync(0xffffffffu, l1, 1);
    l1 += __shfl_xor_sync(0xffffffffu, l1, 2);
    l2 += __shfl_xor_sync(0xffffffffu, l2, 1);
    l2 += __shfl_xor_sync(0xffffffffu, l2, 2);

    int r1 = warp * 16 + (lane >> 2);   // local row 0..63
    int r2 = r1 + 8;
    int cb = 2 * (lane & 3);
    float* o1 = g_opart + ((size_t)bx * 64 + r1) * 256 + cb;
    float* o2 = g_opart + ((size_t)bx * 64 + r2) * 256 + cb;
    #pragma unroll
    for (int j = 0; j < 32; j++) {
        *(float2*)(o1 + j * 8) = make_float2(acc[j][0], acc[j][1]);
        *(float2*)(o2 + j * 8) = make_float2(acc[j][2], acc[j][3]);
    }
    if ((lane & 3) == 0) {
        g_m[bx * 64 + r1] = m1;  g_l[bx * 64 + r1] = l1;
        g_m[bx * 64 + r2] = m2;  g_l[bx * 64 + r2] = l2;
    }
}

// ================= combine kernel (also writes positions) =================
// grid = 392 (region*2 + qtile), 256 threads
__global__ void __launch_bounds__(256)
combine_kernel(float* __restrict__ out, int out_size)
{
    __shared__ float sc[NSPLIT][64];
    const int cta = blockIdx.x;
    const int region = cta >> 1;
    const int qtile  = cta & 1;
    const int base   = cta * NSPLIT;
    const int t = threadIdx.x;

    // positions (second tuple output) from block 0
    if (cta == 0 && t < NREG && out_size >= OUT_ELEMS + POS_ELEMS) {
        out[OUT_ELEMS + 2 * t + 0] = (float)(t / GDIM) * (1.0f / 7.0f);
        out[OUT_ELEMS + 2 * t + 1] = (float)(t % GDIM) * (1.0f / 7.0f);
    }

    if (t < 64) {
        float m0 = g_m[(base + 0) * 64 + t];
        float m1 = g_m[(base + 1) * 64 + t];
        float m2 = g_m[(base + 2) * 64 + t];
        float M  = fmaxf(m0, fmaxf(m1, m2));
        float e0 = __expf(m0 - M), e1 = __expf(m1 - M), e2 = __expf(m2 - M);
        float den = g_l[(base + 0) * 64 + t] * e0
                  + g_l[(base + 1) * 64 + t] * e1
                  + g_l[(base + 2) * 64 + t] * e2;
        float inv = 1.0f / den;
        sc[0][t] = e0 * inv;  sc[1][t] = e1 * inv;  sc[2][t] = e2 * inv;
    }
    __syncthreads();

    // 64 rows x 64 float4 = 4096 float4; 16 per thread
    for (int i = t; i < 4096; i += 256) {
        int row = i >> 6;
        int c4  = i & 63;
        size_t off = ((size_t)base * 64 + row) * 256 + c4 * 4;
        float4 a = *(const float4*)&g_opart[off];
        float4 bq = *(const float4*)&g_opart[off + (size_t)64 * 256];
        float4 c = *(const float4*)&g_opart[off + (size_t)2 * 64 * 256];
        float s0 = sc[0][row], s1 = sc[1][row], s2 = sc[2][row];
        int qg = qtile * 64 + row;
        if (qg < NQ) {
            float4 r;
            r.x = a.x * s0 + bq.x * s1 + c.x * s2;
            r.y = a.y * s0 + bq.y * s1 + c.y * s2;
            r.z = a.z * s0 + bq.z * s1 + c.z * s2;
            r.w = a.w * s0 + bq.w * s1 + c.w * s2;
            *(float4*)&out[((size_t)region * NQ + qg) * CC + c4 * 4] = r;
        }
    }
}

extern "C" void kernel_launch(void* const* d_in, const int* in_sizes, int n_in,
                              void* d_out, int out_size) {
    const float* images  = (const float*)d_in[0];
    const float* queries = (const float*)d_in[1];
    if (n_in >= 2 && in_sizes[0] == NQ * CC) {
        const float* t = images; images = queries; queries = t;
    }
    float* out = (float*)d_out;

    cudaFuncSetAttribute(attn_kernel,
                         cudaFuncAttributeMaxDynamicSharedMemorySize, SMEM_BYTES);

    attn_kernel<<<NWORK, THREADS, SMEM_BYTES>>>(images, queries);
    combine_kernel<<<NREG * NB * 2, 256>>>(out, out_size);
}

// round 16
// speedup vs baseline: 1.5360x; 1.0727x over previous
#include <cuda_runtime.h>
#include <cuda_fp16.h>
#include <cstdint>

#define NB 4
#define GDIM 7
#define NREG 49
#define HH 224
#define CC 256
#define NQ 100
#define HSTRIDE (HH*CC)
#define THREADS 128
#define NSPLIT 3            // key splits per (region, qtile)
#define NWORK (NREG*NB*2*NSPLIT)   // 1176
#define PAD 264             // fp16 row stride (528B -> conflict-free ldmatrix)

#define OUT_ELEMS (NB*NREG*NQ*CC)
#define POS_ELEMS (NREG*2)

// smem byte offsets
#define SQ_HI 0
#define SQ_LO 33792         // 64*264*2
#define SK_HI 67584
#define SK_LO 84480         // SK_HI + 32*264*2
#define SMEM_BYTES 101376   // 2 CTAs/SM
#define QHILO 33792
#define KHILO 16896

// split-K scratch (device globals: no allocation in kernel_launch)
__device__ float g_opart[(size_t)NWORK * 64 * 256];   // unnormalized partial O
__device__ float g_m[NWORK * 64];
__device__ float g_l[NWORK * 64];

// ---------------- helpers ----------------
__device__ __forceinline__ uint32_t smem_u32(const void* p) {
    uint32_t a;
    asm("{ .reg .u64 t; cvta.to.shared.u64 t, %1; cvt.u32.u64 %0, t; }" : "=r"(a) : "l"(p));
    return a;
}
__device__ __forceinline__ uint32_t cvt2h(float a, float b) {  // pack {lo=a, hi=b} fp16x2
    uint32_t r; asm("cvt.rn.f16x2.f32 %0, %2, %1;" : "=r"(r) : "f"(a), "f"(b));
    return r;
}
// fp16 hi/lo split: x = hi + lo with |lo| <= 2^-12 |x|
__device__ __forceinline__ void split2h(float a, float b, uint32_t& hi, uint32_t& lo) {
    hi = cvt2h(a, b);
    __half2 hh = *reinterpret_cast<__half2*>(&hi);
    float2 f = __half22float2(hh);
    lo = cvt2h(a - f.x, b - f.y);
}
__device__ __forceinline__ void ldsm4(uint32_t r[4], uint32_t a) {
    asm volatile("ldmatrix.sync.aligned.m8n8.x4.shared.b16 {%0,%1,%2,%3}, [%4];"
        : "=r"(r[0]), "=r"(r[1]), "=r"(r[2]), "=r"(r[3]) : "r"(a));
}
__device__ __forceinline__ void ldsm4t(uint32_t r[4], uint32_t a) {
    asm volatile("ldmatrix.sync.aligned.m8n8.x4.trans.shared.b16 {%0,%1,%2,%3}, [%4];"
        : "=r"(r[0]), "=r"(r[1]), "=r"(r[2]), "=r"(r[3]) : "r"(a));
}
// f32-accumulate fp16 MMA
__device__ __forceinline__ void mma16816(float* c, const uint32_t* a, uint32_t b0, uint32_t b1) {
    asm volatile("mma.sync.aligned.m16n8k16.row.col.f32.f16.f16.f32 "
        "{%0,%1,%2,%3}, {%4,%5,%6,%7}, {%8,%9}, {%0,%1,%2,%3};"
        : "+f"(c[0]), "+f"(c[1]), "+f"(c[2]), "+f"(c[3])
        : "r"(a[0]), "r"(a[1]), "r"(a[2]), "r"(a[3]), "r"(b0), "r"(b1));
}
// f16-accumulate fp16 MMA (tiny cross terms)
__device__ __forceinline__ void mma16816h(uint32_t* c, const uint32_t* a, uint32_t b0, uint32_t b1) {
    asm volatile("mma.sync.aligned.m16n8k16.row.col.f16.f16.f16.f16 "
        "{%0,%1}, {%2,%3,%4,%5}, {%6,%7}, {%0,%1};"
        : "+r"(c[0]), "+r"(c[1])
        : "r"(a[0]), "r"(a[1]), "r"(a[2]), "r"(a[3]), "r"(b0), "r"(b1));
}

// ================= main attention kernel =================
// grid = 1176: work = region*6 + qtile*3 + split; 128 threads (4 warps x 16 rows)
// 2 CTAs resident per SM; ~4 waves.
// In qtile==1 CTAs, warp 3 covers q-rows 112..127 (all >= NQ) -> skips all MMA work.
__global__ void __launch_bounds__(THREADS, 2)
attn_kernel(const float* __restrict__ images,
            const float* __restrict__ queries)
{
    extern __shared__ char smem[];
    const uint32_t sa = smem_u32(smem);

    const int bx     = blockIdx.x;
    const int region = bx / (2 * NSPLIT);
    const int rem    = bx % (2 * NSPLIT);
    const int qtile  = rem / NSPLIT;
    const int split  = rem % NSPLIT;
    const int p0 = split * 11;                    // 0,11,22
    const int p1 = (split == 2) ? 32 : p0 + 11;   // 11,22,32
    const int b  = region / NREG;
    const int n  = region % NREG;
    const int gi = n / GDIM;
    const int gj = n % GDIM;

    const int tid  = threadIdx.x;
    const int lane = tid & 31;
    const int warp = tid >> 5;          // 0..3, rows warp*16..warp*16+15

    const bool active = (qtile == 0) || (warp < 3);   // warp-uniform

    // ---- stage Q hi/lo: [64 rows][PAD] fp16 each ----
    for (int id = tid; id < 64 * 128; id += THREADS) {   // channel pairs
        int q = id >> 7;
        int c = (id & 127) * 2;
        int qg = qtile * 64 + q;
        float x = 0.0f, y = 0.0f;
        if (qg < NQ) {
            float2 v = *(const float2*)&queries[qg * CC + c];
            x = v.x; y = v.y;
        }
        uint32_t h, l;
        split2h(x, y, h, l);
        uint32_t o = (q * PAD + c) * 2;
        *(uint32_t*)(smem + SQ_HI + o) = h;
        *(uint32_t*)(smem + SQ_LO + o) = l;
    }

    // ---- per-lane ldmatrix base addresses ----
    const uint32_t qA = sa + SQ_HI +
        (((warp * 16) + (lane & 15)) * PAD + (lane >> 4) * 8) * 2;
    const uint32_t kB = sa + SK_HI +
        (((lane & 7) + (lane >> 4) * 8) * PAD + ((lane >> 3) & 1) * 8) * 2;
    const uint32_t vB = sa + SK_HI +
        (((lane & 7) + ((lane >> 3) & 1) * 8) * PAD + (lane >> 4) * 8) * 2;

    const float* imgbase = images + ((size_t)(b * HH + gi * 32) * HH + gj * 32) * CC;

    // ---- state ----
    float acc[32][4];
    #pragma unroll
    for (int j = 0; j < 32; j++)
        #pragma unroll
        for (int k = 0; k < 4; k++) acc[j][k] = 0.0f;
    float m1 = -1e30f, m2 = -1e30f, l1 = 0.0f, l2 = 0.0f;

    for (int p = p0; p < p1; p++) {
        // ---- load 32 keys (one contiguous row-strip); all warps participate ----
        float4 v[16];
        {
            const float4* g0 = (const float4*)(imgbase + (size_t)p * HSTRIDE);
            #pragma unroll
            for (int it = 0; it < 16; it++) v[it] = g0[tid + it * THREADS];
        }
        __syncthreads();                // prev pass compute done
        #pragma unroll
        for (int it = 0; it < 16; it++) {
            int id = tid + it * THREADS;       // 0..2047
            int s = id >> 6, c4 = id & 63;
            uint32_t h0, l0, h1, l1_;
            split2h(v[it].x, v[it].y, h0, l0);
            split2h(v[it].z, v[it].w, h1, l1_);
            uint32_t o = (s * PAD + c4 * 4) * 2;
            *(uint2*)(smem + SK_HI + o) = make_uint2(h0, h1);
            *(uint2*)(smem + SK_LO + o) = make_uint2(l0, l1_);
        }
        __syncthreads();

        if (!active) continue;          // padding warp: barriers done, skip compute

        // ---- QK: S[16 x 32]; hh in f32-acc, cross terms in f16-acc ----
        float shh[4][4];
        uint32_t chl[4][2], clh[4][2];
        #pragma unroll
        for (int j = 0; j < 4; j++) {
            #pragma unroll
            for (int k = 0; k < 4; k++) shh[j][k] = 0.0f;
            chl[j][0] = chl[j][1] = 0u;
            clh[j][0] = clh[j][1] = 0u;
        }

        #pragma unroll
        for (int ks = 0; ks < 16; ks++) {
            uint32_t ah[4], al[4];
            ldsm4(ah, qA + ks * 32);
            ldsm4(al, qA + QHILO + ks * 32);
            #pragma unroll
            for (int j = 0; j < 2; j++) {          // 16 keys per iter
                uint32_t bh[4], bl[4];
                uint32_t ko = kB + j * (16 * PAD * 2) + ks * 32;
                ldsm4(bh, ko);
                ldsm4(bl, ko + KHILO);
                mma16816(shh[2*j],    ah, bh[0], bh[1]);
                mma16816(shh[2*j+1],  ah, bh[2], bh[3]);
                mma16816h(chl[2*j],   ah, bl[0], bl[1]);
                mma16816h(chl[2*j+1], ah, bl[2], bl[3]);
                mma16816h(clh[2*j],   al, bh[0], bh[1]);
                mma16816h(clh[2*j+1], al, bh[2], bh[3]);
            }
        }

        // merge: s = hh + hl + lh
        float s_[4][4];
        #pragma unroll
        for (int j = 0; j < 4; j++) {
            float2 c0 = __half22float2(*reinterpret_cast<__half2*>(&chl[j][0]));
            float2 c1 = __half22float2(*reinterpret_cast<__half2*>(&chl[j][1]));
            float2 d0 = __half22float2(*reinterpret_cast<__half2*>(&clh[j][0]));
            float2 d1 = __half22float2(*reinterpret_cast<__half2*>(&clh[j][1]));
            s_[j][0] = shh[j][0] + c0.x + d0.x;
            s_[j][1] = shh[j][1] + c0.y + d0.y;
            s_[j][2] = shh[j][2] + c1.x + d1.x;
            s_[j][3] = shh[j][3] + c1.y + d1.y;
        }

        // ---- online softmax (rows r=lane>>2 and r+8) ----
        float mx1 = -1e30f, mx2 = -1e30f;
        #pragma unroll
        for (int j = 0; j < 4; j++) {
            mx1 = fmaxf(mx1, fmaxf(s_[j][0], s_[j][1]));
            mx2 = fmaxf(mx2, fmaxf(s_[j][2], s_[j][3]));
        }
        mx1 = fmaxf(mx1, __shfl_xor_sync(0xffffffffu, mx1, 1));
        mx1 = fmaxf(mx1, __shfl_xor_sync(0xffffffffu, mx1, 2));
        mx2 = fmaxf(mx2, __shfl_xor_sync(0xffffffffu, mx2, 1));
        mx2 = fmaxf(mx2, __shfl_xor_sync(0xffffffffu, mx2, 2));
        float m1n = fmaxf(m1, mx1), m2n = fmaxf(m2, mx2);
        float a1 = __expf(m1 - m1n), a2 = __expf(m2 - m2n);
        m1 = m1n; m2 = m2n;

        float sum1 = 0.0f, sum2 = 0.0f;
        #pragma unroll
        for (int j = 0; j < 4; j++) {
            s_[j][0] = __expf(s_[j][0] - m1); sum1 += s_[j][0];
            s_[j][1] = __expf(s_[j][1] - m1); sum1 += s_[j][1];
            s_[j][2] = __expf(s_[j][2] - m2); sum2 += s_[j][2];
            s_[j][3] = __expf(s_[j][3] - m2); sum2 += s_[j][3];
        }
        l1 = l1 * a1 + sum1;
        l2 = l2 * a2 + sum2;

        // skip rescale when max didn't move (warp-uniform branch)
        if (!__all_sync(0xffffffffu, (a1 == 1.0f) && (a2 == 1.0f))) {
            #pragma unroll
            for (int j = 0; j < 32; j++) {
                acc[j][0] *= a1; acc[j][1] *= a1;
                acc[j][2] *= a2; acc[j][3] *= a2;
            }
        }

        // ---- pack P into PV A-fragments: single fp16 (1-term PV) ----
        uint32_t pAh[2][4];
        #pragma unroll
        for (int kk = 0; kk < 2; kk++) {
            pAh[kk][0] = cvt2h(s_[2*kk][0],   s_[2*kk][1]);
            pAh[kk][1] = cvt2h(s_[2*kk][2],   s_[2*kk][3]);
            pAh[kk][2] = cvt2h(s_[2*kk+1][0], s_[2*kk+1][1]);
            pAh[kk][3] = cvt2h(s_[2*kk+1][2], s_[2*kk+1][3]);
        }

        // ---- PV: O += P[16x32] * V[32x256], 1-term fp16, f32 acc ----
        // double-buffered ldsm4t: next nn's B-fragments prefetched under MMAs
        {
            uint32_t b0[4], b1[4];
            ldsm4t(b0, vB);
            ldsm4t(b1, vB + (16 * PAD) * 2);
            #pragma unroll
            for (int nn = 0; nn < 16; nn++) {
                uint32_t n0[4], n1[4];
                if (nn < 15) {
                    ldsm4t(n0, vB + ((nn + 1) * 16) * 2);
                    ldsm4t(n1, vB + (16 * PAD + (nn + 1) * 16) * 2);
                }
                mma16816(acc[2*nn],   pAh[0], b0[0], b0[1]);
                mma16816(acc[2*nn+1], pAh[0], b0[2], b0[3]);
                mma16816(acc[2*nn],   pAh[1], b1[0], b1[1]);
                mma16816(acc[2*nn+1], pAh[1], b1[2], b1[3]);
                #pragma unroll
                for (int q = 0; q < 4; q++) { b0[q] = n0[q]; b1[q] = n1[q]; }
            }
        }
    }

    // ---- epilogue: store UNNORMALIZED partials + (m, l) ----
    if (active) {
        l1 += __shfl_xor_sync(0xffffffffu, l1, 1);
        l1 += __shfl_xor_sync(0xffffffffu, l1, 2);
        l2 += __shfl_xor_sync(0xffffffffu, l2, 1);
        l2 += __shfl_xor_sync(0xffffffffu, l2, 2);

        int r1 = warp * 16 + (lane >> 2);   // local row 0..63
        int r2 = r1 + 8;
        int cb = 2 * (lane & 3);
        float* o1 = g_opart + ((size_t)bx * 64 + r1) * 256 + cb;
        float* o2 = g_opart + ((size_t)bx * 64 + r2) * 256 + cb;
        #pragma unroll
        for (int j = 0; j < 32; j++) {
            *(float2*)(o1 + j * 8) = make_float2(acc[j][0], acc[j][1]);
            *(float2*)(o2 + j * 8) = make_float2(acc[j][2], acc[j][3]);
        }
        if ((lane & 3) == 0) {
            g_m[bx * 64 + r1] = m1;  g_l[bx * 64 + r1] = l1;
            g_m[bx * 64 + r2] = m2;  g_l[bx * 64 + r2] = l2;
        }
    }
}

// ================= combine kernel (also writes positions) =================
// grid = 392 (region*2 + qtile), 256 threads
__global__ void __launch_bounds__(256)
combine_kernel(float* __restrict__ out, int out_size)
{
    __shared__ float sc[NSPLIT][64];
    const int cta = blockIdx.x;
    const int region = cta >> 1;
    const int qtile  = cta & 1;
    const int base   = cta * NSPLIT;
    const int t = threadIdx.x;

    // positions (second tuple output) from block 0
    if (cta == 0 && t < NREG && out_size >= OUT_ELEMS + POS_ELEMS) {
        out[OUT_ELEMS + 2 * t + 0] = (float)(t / GDIM) * (1.0f / 7.0f);
        out[OUT_ELEMS + 2 * t + 1] = (float)(t % GDIM) * (1.0f / 7.0f);
    }

    if (t < 64) {
        // rows >= usable range may hold garbage (skipped padding warp);
        // their sc values are never used because outputs are masked below.
        float m0 = g_m[(base + 0) * 64 + t];
        float m1 = g_m[(base + 1) * 64 + t];
        float m2 = g_m[(base + 2) * 64 + t];
        float M  = fmaxf(m0, fmaxf(m1, m2));
        float e0 = __expf(m0 - M), e1 = __expf(m1 - M), e2 = __expf(m2 - M);
        float den = g_l[(base + 0) * 64 + t] * e0
                  + g_l[(base + 1) * 64 + t] * e1
                  + g_l[(base + 2) * 64 + t] * e2;
        float inv = 1.0f / den;
        sc[0][t] = e0 * inv;  sc[1][t] = e1 * inv;  sc[2][t] = e2 * inv;
    }
    __syncthreads();

    // 64 rows x 64 float4 = 4096 float4; 16 per thread
    for (int i = t; i < 4096; i += 256) {
        int row = i >> 6;
        int c4  = i & 63;
        int qg = qtile * 64 + row;
        if (qg < NQ) {
            size_t off = ((size_t)base * 64 + row) * 256 + c4 * 4;
            float4 a = *(const float4*)&g_opart[off];
            float4 bq = *(const float4*)&g_opart[off + (size_t)64 * 256];
            float4 c = *(const float4*)&g_opart[off + (size_t)2 * 64 * 256];
            float s0 = sc[0][row], s1 = sc[1][row], s2 = sc[2][row];
            float4 r;
            r.x = a.x * s0 + bq.x * s1 + c.x * s2;
            r.y = a.y * s0 + bq.y * s1 + c.y * s2;
            r.z = a.z * s0 + bq.z * s1 + c.z * s2;
            r.w = a.w * s0 + bq.w * s1 + c.w * s2;
            *(float4*)&out[((size_t)region * NQ + qg) * CC + c4 * 4] = r;
        }
    }
}

extern "C" void kernel_launch(void* const* d_in, const int* in_sizes, int n_in,
                              void* d_out, int out_size) {
    const float* images  = (const float*)d_in[0];
    const float* queries = (const float*)d_in[1];
    if (n_in >= 2 && in_sizes[0] == NQ * CC) {
        const float* t = images; images = queries; queries = t;
    }
    float* out = (float*)d_out;

    cudaFuncSetAttribute(attn_kernel,
                         cudaFuncAttributeMaxDynamicSharedMemorySize, SMEM_BYTES);

    attn_kernel<<<NWORK, THREADS, SMEM_BYTES>>>(images, queries);
    combine_kernel<<<NREG * NB * 2, 256>>>(out, out_size);
}

// round 17
// speedup vs baseline: 1.6026x; 1.0434x over previous
#include <cuda_runtime.h>
#include <cuda_fp16.h>
#include <cstdint>

#define NB 4
#define GDIM 7
#define NREG 49
#define HH 224
#define CC 256
#define NQ 100
#define HSTRIDE (HH*CC)
#define THREADS 128
#define NSPLIT 3            // key splits per (region, qtile)
#define NWORK (NREG*NB*2*NSPLIT)   // 1176
#define PAD 264             // fp16 row stride (528B -> conflict-free ldmatrix)

#define OUT_ELEMS (NB*NREG*NQ*CC)
#define POS_ELEMS (NREG*2)

// smem byte offsets
#define SQ_HI 0
#define SQ_LO 33792         // 64*264*2
#define SK_HI 67584
#define SK_LO 84480         // SK_HI + 32*264*2
#define SMEM_BYTES 101376   // 2 CTAs/SM
#define QHILO 33792
#define KHILO 16896

// split-K scratch (device globals: no allocation in kernel_launch)
// partial O stored as packed half2 (channel pairs) -> half the DRAM traffic
__device__ uint32_t g_oparth[(size_t)NWORK * 64 * 128];
__device__ float g_m[NWORK * 64];
__device__ float g_l[NWORK * 64];

// ---------------- helpers ----------------
__device__ __forceinline__ uint32_t smem_u32(const void* p) {
    uint32_t a;
    asm("{ .reg .u64 t; cvta.to.shared.u64 t, %1; cvt.u32.u64 %0, t; }" : "=r"(a) : "l"(p));
    return a;
}
__device__ __forceinline__ uint32_t cvt2h(float a, float b) {  // pack {lo=a, hi=b} fp16x2
    uint32_t r; asm("cvt.rn.f16x2.f32 %0, %2, %1;" : "=r"(r) : "f"(a), "f"(b));
    return r;
}
// fp16 hi/lo split: x = hi + lo with |lo| <= 2^-12 |x|
__device__ __forceinline__ void split2h(float a, float b, uint32_t& hi, uint32_t& lo) {
    hi = cvt2h(a, b);
    __half2 hh = *reinterpret_cast<__half2*>(&hi);
    float2 f = __half22float2(hh);
    lo = cvt2h(a - f.x, b - f.y);
}
__device__ __forceinline__ float2 h2f(uint32_t u) {
    return __half22float2(*reinterpret_cast<__half2*>(&u));
}
__device__ __forceinline__ void ldsm4(uint32_t r[4], uint32_t a) {
    asm volatile("ldmatrix.sync.aligned.m8n8.x4.shared.b16 {%0,%1,%2,%3}, [%4];"
        : "=r"(r[0]), "=r"(r[1]), "=r"(r[2]), "=r"(r[3]) : "r"(a));
}
__device__ __forceinline__ void ldsm4t(uint32_t r[4], uint32_t a) {
    asm volatile("ldmatrix.sync.aligned.m8n8.x4.trans.shared.b16 {%0,%1,%2,%3}, [%4];"
        : "=r"(r[0]), "=r"(r[1]), "=r"(r[2]), "=r"(r[3]) : "r"(a));
}
// f32-accumulate fp16 MMA
__device__ __forceinline__ void mma16816(float* c, const uint32_t* a, uint32_t b0, uint32_t b1) {
    asm volatile("mma.sync.aligned.m16n8k16.row.col.f32.f16.f16.f32 "
        "{%0,%1,%2,%3}, {%4,%5,%6,%7}, {%8,%9}, {%0,%1,%2,%3};"
        : "+f"(c[0]), "+f"(c[1]), "+f"(c[2]), "+f"(c[3])
        : "r"(a[0]), "r"(a[1]), "r"(a[2]), "r"(a[3]), "r"(b0), "r"(b1));
}
// f16-accumulate fp16 MMA (tiny cross terms)
__device__ __forceinline__ void mma16816h(uint32_t* c, const uint32_t* a, uint32_t b0, uint32_t b1) {
    asm volatile("mma.sync.aligned.m16n8k16.row.col.f16.f16.f16.f16 "
        "{%0,%1}, {%2,%3,%4,%5}, {%6,%7}, {%0,%1};"
        : "+r"(c[0]), "+r"(c[1])
        : "r"(a[0]), "r"(a[1]), "r"(a[2]), "r"(a[3]), "r"(b0), "r"(b1));
}

// ================= main attention kernel =================
// grid = 1176: work = region*6 + qtile*3 + split; 128 threads (4 warps x 16 rows)
// 2 CTAs resident per SM; ~4 waves.
// In qtile==1 CTAs, warp 3 covers q-rows 112..127 (all >= NQ) -> skips all MMA work.
__global__ void __launch_bounds__(THREADS, 2)
attn_kernel(const float* __restrict__ images,
            const float* __restrict__ queries)
{
    extern __shared__ char smem[];
    const uint32_t sa = smem_u32(smem);

    const int bx     = blockIdx.x;
    const int region = bx / (2 * NSPLIT);
    const int rem    = bx % (2 * NSPLIT);
    const int qtile  = rem / NSPLIT;
    const int split  = rem % NSPLIT;
    const int p0 = split * 11;                    // 0,11,22
    const int p1 = (split == 2) ? 32 : p0 + 11;   // 11,22,32
    const int b  = region / NREG;
    const int n  = region % NREG;
    const int gi = n / GDIM;
    const int gj = n % GDIM;

    const int tid  = threadIdx.x;
    const int lane = tid & 31;
    const int warp = tid >> 5;          // 0..3, rows warp*16..warp*16+15

    const bool active = (qtile == 0) || (warp < 3);   // warp-uniform

    // ---- stage Q hi/lo: [64 rows][PAD] fp16 each ----
    for (int id = tid; id < 64 * 128; id += THREADS) {   // channel pairs
        int q = id >> 7;
        int c = (id & 127) * 2;
        int qg = qtile * 64 + q;
        float x = 0.0f, y = 0.0f;
        if (qg < NQ) {
            float2 v = *(const float2*)&queries[qg * CC + c];
            x = v.x; y = v.y;
        }
        uint32_t h, l;
        split2h(x, y, h, l);
        uint32_t o = (q * PAD + c) * 2;
        *(uint32_t*)(smem + SQ_HI + o) = h;
        *(uint32_t*)(smem + SQ_LO + o) = l;
    }

    // ---- per-lane ldmatrix base addresses ----
    const uint32_t qA = sa + SQ_HI +
        (((warp * 16) + (lane & 15)) * PAD + (lane >> 4) * 8) * 2;
    const uint32_t kB = sa + SK_HI +
        (((lane & 7) + (lane >> 4) * 8) * PAD + ((lane >> 3) & 1) * 8) * 2;
    const uint32_t vB = sa + SK_HI +
        (((lane & 7) + ((lane >> 3) & 1) * 8) * PAD + (lane >> 4) * 8) * 2;

    const float* imgbase = images + ((size_t)(b * HH + gi * 32) * HH + gj * 32) * CC;

    // ---- state ----
    float acc[32][4];
    #pragma unroll
    for (int j = 0; j < 32; j++)
        #pragma unroll
        for (int k = 0; k < 4; k++) acc[j][k] = 0.0f;
    float m1 = -1e30f, m2 = -1e30f, l1 = 0.0f, l2 = 0.0f;

    for (int p = p0; p < p1; p++) {
        // ---- load 32 keys (one contiguous row-strip); all warps participate ----
        float4 v[16];
        {
            const float4* g0 = (const float4*)(imgbase + (size_t)p * HSTRIDE);
            #pragma unroll
            for (int it = 0; it < 16; it++) v[it] = g0[tid + it * THREADS];
        }
        __syncthreads();                // prev pass compute done
        #pragma unroll
        for (int it = 0; it < 16; it++) {
            int id = tid + it * THREADS;       // 0..2047
            int s = id >> 6, c4 = id & 63;
            uint32_t h0, l0, h1, l1_;
            split2h(v[it].x, v[it].y, h0, l0);
            split2h(v[it].z, v[it].w, h1, l1_);
            uint32_t o = (s * PAD + c4 * 4) * 2;
            *(uint2*)(smem + SK_HI + o) = make_uint2(h0, h1);
            *(uint2*)(smem + SK_LO + o) = make_uint2(l0, l1_);
        }
        __syncthreads();

        if (!active) continue;          // padding warp: barriers done, skip compute

        // ---- QK: S[16 x 32]; hh in f32-acc, cross terms in f16-acc ----
        float shh[4][4];
        uint32_t chl[4][2], clh[4][2];
        #pragma unroll
        for (int j = 0; j < 4; j++) {
            #pragma unroll
            for (int k = 0; k < 4; k++) shh[j][k] = 0.0f;
            chl[j][0] = chl[j][1] = 0u;
            clh[j][0] = clh[j][1] = 0u;
        }

        #pragma unroll
        for (int ks = 0; ks < 16; ks++) {
            uint32_t ah[4], al[4];
            ldsm4(ah, qA + ks * 32);
            ldsm4(al, qA + QHILO + ks * 32);
            #pragma unroll
            for (int j = 0; j < 2; j++) {          // 16 keys per iter
                uint32_t bh[4], bl[4];
                uint32_t ko = kB + j * (16 * PAD * 2) + ks * 32;
                ldsm4(bh, ko);
                ldsm4(bl, ko + KHILO);
                mma16816(shh[2*j],    ah, bh[0], bh[1]);
                mma16816(shh[2*j+1],  ah, bh[2], bh[3]);
                mma16816h(chl[2*j],   ah, bl[0], bl[1]);
                mma16816h(chl[2*j+1], ah, bl[2], bl[3]);
                mma16816h(clh[2*j],   al, bh[0], bh[1]);
                mma16816h(clh[2*j+1], al, bh[2], bh[3]);
            }
        }

        // merge: s = hh + hl + lh
        float s_[4][4];
        #pragma unroll
        for (int j = 0; j < 4; j++) {
            float2 c0 = h2f(chl[j][0]), c1 = h2f(chl[j][1]);
            float2 d0 = h2f(clh[j][0]), d1 = h2f(clh[j][1]);
            s_[j][0] = shh[j][0] + c0.x + d0.x;
            s_[j][1] = shh[j][1] + c0.y + d0.y;
            s_[j][2] = shh[j][2] + c1.x + d1.x;
            s_[j][3] = shh[j][3] + c1.y + d1.y;
        }

        // ---- online softmax (rows r=lane>>2 and r+8) ----
        float mx1 = -1e30f, mx2 = -1e30f;
        #pragma unroll
        for (int j = 0; j < 4; j++) {
            mx1 = fmaxf(mx1, fmaxf(s_[j][0], s_[j][1]));
            mx2 = fmaxf(mx2, fmaxf(s_[j][2], s_[j][3]));
        }
        mx1 = fmaxf(mx1, __shfl_xor_sync(0xffffffffu, mx1, 1));
        mx1 = fmaxf(mx1, __shfl_xor_sync(0xffffffffu, mx1, 2));
        mx2 = fmaxf(mx2, __shfl_xor_sync(0xffffffffu, mx2, 1));
        mx2 = fmaxf(mx2, __shfl_xor_sync(0xffffffffu, mx2, 2));
        float m1n = fmaxf(m1, mx1), m2n = fmaxf(m2, mx2);
        float a1 = __expf(m1 - m1n), a2 = __expf(m2 - m2n);
        m1 = m1n; m2 = m2n;

        float sum1 = 0.0f, sum2 = 0.0f;
        #pragma unroll
        for (int j = 0; j < 4; j++) {
            s_[j][0] = __expf(s_[j][0] - m1); sum1 += s_[j][0];
            s_[j][1] = __expf(s_[j][1] - m1); sum1 += s_[j][1];
            s_[j][2] = __expf(s_[j][2] - m2); sum2 += s_[j][2];
            s_[j][3] = __expf(s_[j][3] - m2); sum2 += s_[j][3];
        }
        l1 = l1 * a1 + sum1;
        l2 = l2 * a2 + sum2;

        // skip rescale when max didn't move (warp-uniform branch)
        if (!__all_sync(0xffffffffu, (a1 == 1.0f) && (a2 == 1.0f))) {
            #pragma unroll
            for (int j = 0; j < 32; j++) {
                acc[j][0] *= a1; acc[j][1] *= a1;
                acc[j][2] *= a2; acc[j][3] *= a2;
            }
        }

        // ---- pack P into PV A-fragments: single fp16 (1-term PV) ----
        uint32_t pAh[2][4];
        #pragma unroll
        for (int kk = 0; kk < 2; kk++) {
            pAh[kk][0] = cvt2h(s_[2*kk][0],   s_[2*kk][1]);
            pAh[kk][1] = cvt2h(s_[2*kk][2],   s_[2*kk][3]);
            pAh[kk][2] = cvt2h(s_[2*kk+1][0], s_[2*kk+1][1]);
            pAh[kk][3] = cvt2h(s_[2*kk+1][2], s_[2*kk+1][3]);
        }

        // ---- PV: O += P[16x32] * V[32x256], 1-term fp16, f32 acc ----
        // double-buffered ldsm4t: next nn's B-fragments prefetched under MMAs
        {
            uint32_t b0[4], b1[4];
            ldsm4t(b0, vB);
            ldsm4t(b1, vB + (16 * PAD) * 2);
            #pragma unroll
            for (int nn = 0; nn < 16; nn++) {
                uint32_t n0[4], n1[4];
                if (nn < 15) {
                    ldsm4t(n0, vB + ((nn + 1) * 16) * 2);
                    ldsm4t(n1, vB + (16 * PAD + (nn + 1) * 16) * 2);
                }
                mma16816(acc[2*nn],   pAh[0], b0[0], b0[1]);
                mma16816(acc[2*nn+1], pAh[0], b0[2], b0[3]);
                mma16816(acc[2*nn],   pAh[1], b1[0], b1[1]);
                mma16816(acc[2*nn+1], pAh[1], b1[2], b1[3]);
                #pragma unroll
                for (int q = 0; q < 4; q++) { b0[q] = n0[q]; b1[q] = n1[q]; }
            }
        }
    }

    // ---- epilogue: store UNNORMALIZED partials as half2 + (m, l) fp32 ----
    if (active) {
        l1 += __shfl_xor_sync(0xffffffffu, l1, 1);
        l1 += __shfl_xor_sync(0xffffffffu, l1, 2);
        l2 += __shfl_xor_sync(0xffffffffu, l2, 1);
        l2 += __shfl_xor_sync(0xffffffffu, l2, 2);

        int r1 = warp * 16 + (lane >> 2);   // local row 0..63
        int r2 = r1 + 8;
        int pb = lane & 3;                  // channel-pair base (cb/2)
        uint32_t* o1 = g_oparth + ((size_t)bx * 64 + r1) * 128 + pb;
        uint32_t* o2 = g_oparth + ((size_t)bx * 64 + r2) * 128 + pb;
        #pragma unroll
        for (int j = 0; j < 32; j++) {
            o1[j * 4] = cvt2h(acc[j][0], acc[j][1]);
            o2[j * 4] = cvt2h(acc[j][2], acc[j][3]);
        }
        if ((lane & 3) == 0) {
            g_m[bx * 64 + r1] = m1;  g_l[bx * 64 + r1] = l1;
            g_m[bx * 64 + r2] = m2;  g_l[bx * 64 + r2] = l2;
        }
    }
}

// ================= combine kernel (also writes positions) =================
// grid = 784: cta>>1 = (region*2 + qtile), cta&1 = row half (32 rows each)
__global__ void __launch_bounds__(256)
combine_kernel(float* __restrict__ out, int out_size)
{
    __shared__ float sc[NSPLIT][32];
    const int cta  = blockIdx.x;
    const int pair = cta >> 1;          // 0..391
    const int half = cta & 1;           // rows half*32 .. half*32+31
    const int region = pair >> 1;
    const int qtile  = pair & 1;
    const int base   = pair * NSPLIT;
    const int rbase  = half * 32;
    const int t = threadIdx.x;

    // positions (second tuple output) from block 0
    if (cta == 0 && t < NREG && out_size >= OUT_ELEMS + POS_ELEMS) {
        out[OUT_ELEMS + 2 * t + 0] = (float)(t / GDIM) * (1.0f / 7.0f);
        out[OUT_ELEMS + 2 * t + 1] = (float)(t % GDIM) * (1.0f / 7.0f);
    }

    if (t < 32) {
        int row = rbase + t;
        float m0 = g_m[(base + 0) * 64 + row];
        float m1 = g_m[(base + 1) * 64 + row];
        float m2 = g_m[(base + 2) * 64 + row];
        float M  = fmaxf(m0, fmaxf(m1, m2));
        float e0 = __expf(m0 - M), e1 = __expf(m1 - M), e2 = __expf(m2 - M);
        float den = g_l[(base + 0) * 64 + row] * e0
                  + g_l[(base + 1) * 64 + row] * e1
                  + g_l[(base + 2) * 64 + row] * e2;
        float inv = 1.0f / den;
        sc[0][t] = e0 * inv;  sc[1][t] = e1 * inv;  sc[2][t] = e2 * inv;
    }
    __syncthreads();

    // 32 rows x 64 float4-chunks = 2048; 8 per thread
    for (int i = t; i < 2048; i += 256) {
        int lrow = i >> 6;
        int row  = rbase + lrow;
        int c4   = i & 63;
        int qg = qtile * 64 + row;
        if (qg < NQ) {
            size_t off = ((size_t)base * 64 + row) * 128 + c4 * 2;   // pair index
            uint2 ua = *(const uint2*)&g_oparth[off];
            uint2 ub = *(const uint2*)&g_oparth[off + (size_t)64 * 128];
            uint2 uc = *(const uint2*)&g_oparth[off + (size_t)2 * 64 * 128];
            float2 a01 = h2f(ua.x), a23 = h2f(ua.y);
            float2 b01 = h2f(ub.x), b23 = h2f(ub.y);
            float2 c01 = h2f(uc.x), c23 = h2f(uc.y);
            float s0 = sc[0][lrow], s1 = sc[1][lrow], s2 = sc[2][lrow];
            float4 r;
            r.x = a01.x * s0 + b01.x * s1 + c01.x * s2;
            r.y = a01.y * s0 + b01.y * s1 + c01.y * s2;
            r.z = a23.x * s0 + b23.x * s1 + c23.x * s2;
            r.w = a23.y * s0 + b23.y * s1 + c23.y * s2;
            *(float4*)&out[((size_t)region * NQ + qg) * CC + c4 * 4] = r;
        }
    }
}

extern "C" void kernel_launch(void* const* d_in, const int* in_sizes, int n_in,
                              void* d_out, int out_size) {
    const float* images  = (const float*)d_in[0];
    const float* queries = (const float*)d_in[1];
    if (n_in >= 2 && in_sizes[0] == NQ * CC) {
        const float* t = images; images = queries; queries = t;
    }
    float* out = (float*)d_out;

    cudaFuncSetAttribute(attn_kernel,
                         cudaFuncAttributeMaxDynamicSharedMemorySize, SMEM_BYTES);

    attn_kernel<<<NWORK, THREADS, SMEM_BYTES>>>(images, queries);
    combine_kernel<<<NREG * NB * 2 * 2, 256>>>(out, out_size);
}